// round 4
// baseline (speedup 1.0000x reference)
#include <cuda_runtime.h>
#include <math.h>

// Problem constants
#define NFEAT   256
#define NHID    128
#define NCLASS  40
#define MAXN    100000
#define MAXE    3200000

// ---------------------------------------------------------------------------
// Static device scratch (allocation-free rule: __device__ globals)
// ---------------------------------------------------------------------------
__device__ int   g_cnt[MAXN];
__device__ int   g_rowptr[MAXN + 1];
__device__ int   g_next[MAXN];
__device__ int   g_csr[MAXE];
__device__ float g_neigh1[(size_t)MAXN * NFEAT];   // 102.4 MB
__device__ float g_h1[(size_t)MAXN * NHID];        // 51.2 MB
__device__ float g_neigh2[(size_t)MAXN * NHID];    // 51.2 MB
__device__ float g_h2[(size_t)MAXN * NHID];        // 51.2 MB
__device__ float g_w1t[2 * NFEAT * NHID];          // W1^T  [512,128]
__device__ float g_w2t[2 * NHID * NHID];           // W2^T  [256,128]

// ---------------------------------------------------------------------------
// Small utility kernels
// ---------------------------------------------------------------------------
__global__ void zero_cnt_kernel(int n) {
    int i = blockIdx.x * blockDim.x + threadIdx.x;
    if (i < n) g_cnt[i] = 0;
}

__global__ void count_kernel(const int* __restrict__ rows, int e) {
    int i = blockIdx.x * blockDim.x + threadIdx.x;
    if (i < e) atomicAdd(&g_cnt[rows[i]], 1);
}

// Single-block exclusive scan over g_cnt -> g_rowptr (also copies into g_next).
// Warp-shuffle scan per chunk of 1024, carried across chunks.
__global__ void scan_kernel(int n, int etot) {
    __shared__ int wsum[32];
    __shared__ int carry_s;
    const int tid  = threadIdx.x;
    const int lane = tid & 31;
    const int wid  = tid >> 5;
    if (tid == 0) carry_s = 0;
    __syncthreads();

    for (int base = 0; base < n; base += 1024) {
        int i = base + tid;
        int v = (i < n) ? g_cnt[i] : 0;
        int incl = v;
        #pragma unroll
        for (int off = 1; off < 32; off <<= 1) {
            int t = __shfl_up_sync(0xffffffffu, incl, off);
            if (lane >= off) incl += t;
        }
        if (lane == 31) wsum[wid] = incl;
        __syncthreads();
        if (wid == 0) {
            int s  = wsum[lane];
            int si = s;
            #pragma unroll
            for (int off = 1; off < 32; off <<= 1) {
                int t = __shfl_up_sync(0xffffffffu, si, off);
                if (lane >= off) si += t;
            }
            wsum[lane] = si - s;   // exclusive warp offsets
        }
        __syncthreads();
        int c    = carry_s;
        int excl = c + wsum[wid] + (incl - v);
        if (i < n) { g_rowptr[i] = excl; g_next[i] = excl; }
        __syncthreads();                          // all reads of carry_s/wsum done
        if (tid == 1023) carry_s = c + wsum[31] + incl;   // carry += block total
        __syncthreads();
    }
    if (tid == 0) g_rowptr[n] = etot;
}

__global__ void fill_kernel(const int* __restrict__ rows,
                            const int* __restrict__ cols, int e) {
    int i = blockIdx.x * blockDim.x + threadIdx.x;
    if (i < e) {
        int p = atomicAdd(&g_next[rows[i]], 1);
        g_csr[p] = cols[i];
    }
}

// Wt[k*128 + j] = W[j*K + k]   (W row-major [128, K])
__global__ void transpose_kernel(const float* __restrict__ W,
                                 float* __restrict__ Wt, int K) {
    int idx = blockIdx.x * blockDim.x + threadIdx.x;
    if (idx < K * NHID) {
        int k = idx / NHID, j = idx % NHID;
        Wt[idx] = W[(size_t)j * K + k];
    }
}

// ---------------------------------------------------------------------------
// SpMM: out[i,:] = (sum_{j in N(i)} src[j,:]) / (deg[i] + 1)
// One warp per destination node. F4 = row width in float4 (64 for 256 feats,
// 32 for 128 feats).
// ---------------------------------------------------------------------------
template <int F4>
__global__ __launch_bounds__(256) void spmm_kernel(const float* __restrict__ src,
                                                   float* __restrict__ out, int n) {
    int w = (blockIdx.x * blockDim.x + threadIdx.x) >> 5;
    if (w >= n) return;
    int lane = threadIdx.x & 31;
    int s = g_rowptr[w], e = g_rowptr[w + 1];
    float4 acc0 = make_float4(0.f, 0.f, 0.f, 0.f);
    float4 acc1 = make_float4(0.f, 0.f, 0.f, 0.f);
    const float4* sp = (const float4*)src;
    for (int k = s; k < e; ++k) {
        int j = __ldg(&g_csr[k]);
        const float4* r = sp + (size_t)j * F4;
        float4 a = __ldg(&r[lane]);
        acc0.x += a.x; acc0.y += a.y; acc0.z += a.z; acc0.w += a.w;
        if (F4 == 64) {
            float4 b = __ldg(&r[lane + 32]);
            acc1.x += b.x; acc1.y += b.y; acc1.z += b.z; acc1.w += b.w;
        }
    }
    float inv = 1.0f / (float)(e - s + 1);
    float4* op = (float4*)out + (size_t)w * F4;
    op[lane] = make_float4(acc0.x * inv, acc0.y * inv, acc0.z * inv, acc0.w * inv);
    if (F4 == 64)
        op[lane + 32] = make_float4(acc1.x * inv, acc1.y * inv, acc1.z * inv, acc1.w * inv);
}

// ---------------------------------------------------------------------------
// C[n,128] = relu( [A1 | A2][n, K1+K2] @ Bt[K1+K2, 128] )
// Block: 128 rows x 128 cols, 256 threads, 8x8 microtile, BK=8.
// A1/A2 row-major with leading dims K1/K2 (the virtual concat).
// ---------------------------------------------------------------------------
__global__ __launch_bounds__(256) void gemm_relu_kernel(
    const float* __restrict__ A1, const float* __restrict__ A2,
    int K1, int K2, const float* __restrict__ Bt,
    float* __restrict__ C, int n) {
    __shared__ float As[8][128];
    __shared__ float Bs[8][128];
    const int tid  = threadIdx.x;
    const int tx   = tid & 15;           // col group
    const int ty   = tid >> 4;           // row group
    const int row0 = blockIdx.x * 128;
    const int arow = tid >> 1;           // 0..127
    const int kh   = (tid & 1) << 2;     // 0 or 4
    const int bkk  = tid >> 5;           // 0..7
    const int bcol = (tid & 31) << 2;    // 0..124

    float acc[8][8];
    #pragma unroll
    for (int i = 0; i < 8; ++i)
        #pragma unroll
        for (int j = 0; j < 8; ++j) acc[i][j] = 0.f;

    const int K = K1 + K2;
    for (int k0 = 0; k0 < K; k0 += 8) {
        const float* Ab; int ld, kk0;
        if (k0 < K1) { Ab = A1; ld = K1; kk0 = k0; }
        else         { Ab = A2; ld = K2; kk0 = k0 - K1; }
        int grow = row0 + arow;
        float4 av = make_float4(0.f, 0.f, 0.f, 0.f);
        if (grow < n)
            av = *(const float4*)(Ab + (size_t)grow * ld + kk0 + kh);
        float4 bv = *(const float4*)(Bt + (size_t)(k0 + bkk) * 128 + bcol);

        __syncthreads();
        As[kh + 0][arow] = av.x;
        As[kh + 1][arow] = av.y;
        As[kh + 2][arow] = av.z;
        As[kh + 3][arow] = av.w;
        *(float4*)&Bs[bkk][bcol] = bv;
        __syncthreads();

        #pragma unroll
        for (int kk = 0; kk < 8; ++kk) {
            float a[8], b[8];
            #pragma unroll
            for (int i = 0; i < 8; ++i) a[i] = As[kk][ty * 8 + i];
            #pragma unroll
            for (int j = 0; j < 8; ++j) b[j] = Bs[kk][tx * 8 + j];
            #pragma unroll
            for (int i = 0; i < 8; ++i)
                #pragma unroll
                for (int j = 0; j < 8; ++j)
                    acc[i][j] = fmaf(a[i], b[j], acc[i][j]);
        }
    }

    #pragma unroll
    for (int i = 0; i < 8; ++i) {
        int row = row0 + ty * 8 + i;
        if (row < n) {
            float4 v0 = make_float4(fmaxf(acc[i][0], 0.f), fmaxf(acc[i][1], 0.f),
                                    fmaxf(acc[i][2], 0.f), fmaxf(acc[i][3], 0.f));
            float4 v1 = make_float4(fmaxf(acc[i][4], 0.f), fmaxf(acc[i][5], 0.f),
                                    fmaxf(acc[i][6], 0.f), fmaxf(acc[i][7], 0.f));
            *(float4*)(C + (size_t)row * 128 + tx * 8)     = v0;
            *(float4*)(C + (size_t)row * 128 + tx * 8 + 4) = v1;
        }
    }
}

// ---------------------------------------------------------------------------
// Fused MLP + log_softmax. Warp per node; W [40,128] staged in shared with
// pad 129 -> bank = (c+k) mod 32 -> conflict-free. Shuffle reductions.
// ---------------------------------------------------------------------------
#define MLP_NPW 16   // nodes per warp

__global__ __launch_bounds__(256) void mlp_kernel(const float* __restrict__ h2,
                                                  const float* __restrict__ W,
                                                  const float* __restrict__ bias,
                                                  float* __restrict__ out, int n) {
    __shared__ float Ws[NCLASS * 129];
    const int tid = threadIdx.x;
    for (int i = tid; i < NCLASS * 128; i += 256) {
        int c = i >> 7, k = i & 127;
        Ws[c * 129 + k] = W[i];
    }
    __syncthreads();

    const int lane = tid & 31;
    const int wid  = tid >> 5;
    const int warp_global = blockIdx.x * 8 + wid;
    float b0 = __ldg(&bias[lane]);                          // lane < 32 < 40
    float b1 = (lane < NCLASS - 32) ? __ldg(&bias[lane + 32]) : 0.f;

    for (int it = 0; it < MLP_NPW; ++it) {
        int node = warp_global * MLP_NPW + it;
        if (node >= n) break;
        const float* hr = h2 + (size_t)node * 128;
        float v0 = b0, v1 = b1;
        #pragma unroll 4
        for (int k = 0; k < 128; ++k) {
            float h = __ldg(&hr[k]);
            v0 = fmaf(h, Ws[lane * 129 + k], v0);
            if (lane < 8) v1 = fmaf(h, Ws[(lane + 32) * 129 + k], v1);
        }
        float m = v0;
        if (lane < 8) m = fmaxf(m, v1);
        #pragma unroll
        for (int off = 16; off >= 1; off >>= 1)
            m = fmaxf(m, __shfl_xor_sync(0xffffffffu, m, off));
        float s = expf(v0 - m) + ((lane < 8) ? expf(v1 - m) : 0.f);
        #pragma unroll
        for (int off = 16; off >= 1; off >>= 1)
            s += __shfl_xor_sync(0xffffffffu, s, off);
        float ls = logf(s);
        float* orow = out + (size_t)node * NCLASS;
        orow[lane] = v0 - m - ls;
        if (lane < 8) orow[32 + lane] = v1 - m - ls;
    }
}

// ---------------------------------------------------------------------------
// Launch
// ---------------------------------------------------------------------------
extern "C" void kernel_launch(void* const* d_in, const int* in_sizes, int n_in,
                              void* d_out, int out_size) {
    const float* x    = (const float*)d_in[0];
    const float* W1   = (const float*)d_in[1];
    const float* W2   = (const float*)d_in[2];
    const float* mlpW = (const float*)d_in[3];
    const float* mlpb = (const float*)d_in[4];
    const int*   rows = (const int*)d_in[5];
    const int*   cols = (const int*)d_in[6];
    const int n = in_sizes[0] / NFEAT;
    const int e = in_sizes[5];
    float* out = (float*)d_out;

    void *p_neigh1, *p_h1, *p_neigh2, *p_h2, *p_w1t, *p_w2t;
    cudaGetSymbolAddress(&p_neigh1, g_neigh1);
    cudaGetSymbolAddress(&p_h1, g_h1);
    cudaGetSymbolAddress(&p_neigh2, g_neigh2);
    cudaGetSymbolAddress(&p_h2, g_h2);
    cudaGetSymbolAddress(&p_w1t, g_w1t);
    cudaGetSymbolAddress(&p_w2t, g_w2t);

    // Weight transposes (independent; tiny)
    transpose_kernel<<<(2 * NFEAT * NHID + 255) / 256, 256>>>(W1, (float*)p_w1t, 2 * NFEAT);
    transpose_kernel<<<(2 * NHID * NHID + 255) / 256, 256>>>(W2, (float*)p_w2t, 2 * NHID);

    // CSR build
    zero_cnt_kernel<<<(n + 255) / 256, 256>>>(n);
    count_kernel<<<(e + 255) / 256, 256>>>(rows, e);
    scan_kernel<<<1, 1024>>>(n, e);
    fill_kernel<<<(e + 255) / 256, 256>>>(rows, cols, e);

    // Layer 1
    int spmm_blocks = (n * 32 + 255) / 256;
    spmm_kernel<64><<<spmm_blocks, 256>>>(x, (float*)p_neigh1, n);
    gemm_relu_kernel<<<(n + 127) / 128, 256>>>(x, (const float*)p_neigh1,
                                               NFEAT, NFEAT, (const float*)p_w1t,
                                               (float*)p_h1, n);
    // Layer 2
    spmm_kernel<32><<<spmm_blocks, 256>>>((const float*)p_h1, (float*)p_neigh2, n);
    gemm_relu_kernel<<<(n + 127) / 128, 256>>>((const float*)p_h1, (const float*)p_neigh2,
                                               NHID, NHID, (const float*)p_w2t,
                                               (float*)p_h2, n);
    // MLP + log_softmax
    int mlp_warps  = (n + MLP_NPW - 1) / MLP_NPW;
    int mlp_blocks = (mlp_warps + 7) / 8;
    mlp_kernel<<<mlp_blocks, 256>>>((const float*)p_h2, mlpW, mlpb, out, n);
}

// round 6
// speedup vs baseline: 1.5537x; 1.5537x over previous
#include <cuda_runtime.h>
#include <cuda_bf16.h>
#include <math.h>
#include <stdint.h>

// Problem constants
#define NFEAT   256
#define NHID    128
#define NCLASS  40
#define MAXN    100000
#define MAXE    3200000

// ---------------------------------------------------------------------------
// Static device scratch (allocation-free rule: __device__ globals)
// ---------------------------------------------------------------------------
__device__ int   g_cnt[MAXN];
__device__ int   g_rowptr[MAXN + 1];
__device__ int   g_next[MAXN];
__device__ int   g_csr[MAXE];
__device__ float g_s[(size_t)MAXN * NHID];     // self-projection   (51.2 MB)
__device__ float g_z[(size_t)MAXN * NHID];     // neigh-projection  (51.2 MB)
__device__ float g_h1[(size_t)MAXN * NHID];
__device__ float g_h2[(size_t)MAXN * NHID];
// bf16-split weights, layout [128 out-rows, K in-cols] K-major (= torch native)
__device__ __nv_bfloat16 g_b1s_hi[128 * 256], g_b1s_lo[128 * 256];
__device__ __nv_bfloat16 g_b1n_hi[128 * 256], g_b1n_lo[128 * 256];
__device__ __nv_bfloat16 g_b2s_hi[128 * 128], g_b2s_lo[128 * 128];
__device__ __nv_bfloat16 g_b2n_hi[128 * 128], g_b2n_lo[128 * 128];

// ---------------------------------------------------------------------------
// Helpers
// ---------------------------------------------------------------------------
__device__ __forceinline__ uint32_t smem_u32(const void* p) {
    uint32_t a;
    asm("{ .reg .u64 t; cvta.to.shared.u64 t, %1; cvt.u32.u64 %0, t; }"
        : "=r"(a) : "l"(p));
    return a;
}

// SW128-style XOR swizzle: bits[6:4] ^= bits[9:7] (conflict-free ldmatrix)
#define SWZ(x) ((x) ^ (((x) >> 3) & 0x70))

__device__ __forceinline__ void ldsm_x4(uint32_t addr, uint32_t& r0, uint32_t& r1,
                                        uint32_t& r2, uint32_t& r3) {
    asm volatile("ldmatrix.sync.aligned.m8n8.x4.shared.b16 {%0,%1,%2,%3}, [%4];"
                 : "=r"(r0), "=r"(r1), "=r"(r2), "=r"(r3) : "r"(addr));
}

__device__ __forceinline__ void mma_bf16(float* d, const uint32_t* a,
                                         uint32_t b0, uint32_t b1) {
    asm volatile(
        "mma.sync.aligned.m16n8k16.row.col.f32.bf16.bf16.f32 "
        "{%0,%1,%2,%3}, {%4,%5,%6,%7}, {%8,%9}, {%0,%1,%2,%3};"
        : "+f"(d[0]), "+f"(d[1]), "+f"(d[2]), "+f"(d[3])
        : "r"(a[0]), "r"(a[1]), "r"(a[2]), "r"(a[3]), "r"(b0), "r"(b1));
}

// ---------------------------------------------------------------------------
// CSR build
// ---------------------------------------------------------------------------
__global__ void zero_cnt_kernel(int n) {
    int i = blockIdx.x * blockDim.x + threadIdx.x;
    if (i < n) g_cnt[i] = 0;
}

__global__ void count_kernel(const int* __restrict__ rows, int e) {
    int i = blockIdx.x * blockDim.x + threadIdx.x;
    if (i < e) atomicAdd(&g_cnt[rows[i]], 1);
}

__global__ void scan_kernel(int n, int etot) {
    __shared__ int wsum[32];
    __shared__ int carry_s;
    const int tid  = threadIdx.x;
    const int lane = tid & 31;
    const int wid  = tid >> 5;
    if (tid == 0) carry_s = 0;
    __syncthreads();

    for (int base = 0; base < n; base += 1024) {
        int i = base + tid;
        int v = (i < n) ? g_cnt[i] : 0;
        int incl = v;
        #pragma unroll
        for (int off = 1; off < 32; off <<= 1) {
            int t = __shfl_up_sync(0xffffffffu, incl, off);
            if (lane >= off) incl += t;
        }
        if (lane == 31) wsum[wid] = incl;
        __syncthreads();
        if (wid == 0) {
            int s  = wsum[lane];
            int si = s;
            #pragma unroll
            for (int off = 1; off < 32; off <<= 1) {
                int t = __shfl_up_sync(0xffffffffu, si, off);
                if (lane >= off) si += t;
            }
            wsum[lane] = si - s;
        }
        __syncthreads();
        int c    = carry_s;
        int excl = c + wsum[wid] + (incl - v);
        if (i < n) { g_rowptr[i] = excl; g_next[i] = excl; }
        __syncthreads();
        if (tid == 1023) carry_s = c + wsum[31] + incl;
        __syncthreads();
    }
    if (tid == 0) g_rowptr[n] = etot;
}

__global__ void fill_kernel(const int* __restrict__ rows,
                            const int* __restrict__ cols, int e) {
    int i = blockIdx.x * blockDim.x + threadIdx.x;
    if (i < e) {
        int p = atomicAdd(&g_next[rows[i]], 1);
        g_csr[p] = cols[i];
    }
}

// ---------------------------------------------------------------------------
// Weight prep: split fp32 -> (hi, lo) bf16, slicing concat halves.
// ---------------------------------------------------------------------------
__global__ void prep_w1_kernel(const float* __restrict__ W1) {
    int idx = blockIdx.x * blockDim.x + threadIdx.x;
    if (idx >= 128 * 256) return;
    int j = idx >> 8, k = idx & 255;
    float a = W1[j * 512 + k];
    __nv_bfloat16 ha = __float2bfloat16(a);
    g_b1s_hi[idx] = ha;
    g_b1s_lo[idx] = __float2bfloat16(a - __bfloat162float(ha));
    float b = W1[j * 512 + 256 + k];
    __nv_bfloat16 hb = __float2bfloat16(b);
    g_b1n_hi[idx] = hb;
    g_b1n_lo[idx] = __float2bfloat16(b - __bfloat162float(hb));
}

__global__ void prep_w2_kernel(const float* __restrict__ W2) {
    int idx = blockIdx.x * blockDim.x + threadIdx.x;
    if (idx >= 128 * 128) return;
    int j = idx >> 7, k = idx & 127;
    float a = W2[j * 256 + k];
    __nv_bfloat16 ha = __float2bfloat16(a);
    g_b2s_hi[idx] = ha;
    g_b2s_lo[idx] = __float2bfloat16(a - __bfloat162float(ha));
    float b = W2[j * 256 + 128 + k];
    __nv_bfloat16 hb = __float2bfloat16(b);
    g_b2n_hi[idx] = hb;
    g_b2n_lo[idx] = __float2bfloat16(b - __bfloat162float(hb));
}

// ---------------------------------------------------------------------------
// mma.sync bf16 split-3 GEMM:  C[128-row blk, 128] = A[n,K] @ B[128,K]^T
// Block 128x128, 8 warps (4x2), warp tile 32x64, K chunked by 64 in smem.
// A fp32 converted to hi/lo bf16 on the fly; B pre-split in gmem.
// gridDim.y selects (B, C) pair (self / neigh projections).
// ---------------------------------------------------------------------------
template <int K>
__global__ __launch_bounds__(256) void mma_gemm_kernel(
    const float* __restrict__ A,
    const __nv_bfloat16* __restrict__ B0h, const __nv_bfloat16* __restrict__ B0l,
    float* __restrict__ C0,
    const __nv_bfloat16* __restrict__ B1h, const __nv_bfloat16* __restrict__ B1l,
    float* __restrict__ C1,
    int n) {
    extern __shared__ char smem[];
    constexpr int AH = 0, AL = 16384, BH = 32768, BL = 49152;
    const uint32_t sb = smem_u32(smem);
    const int tid    = threadIdx.x;
    const int lane   = tid & 31;
    const int wid    = tid >> 5;
    const int warp_m = wid & 3;         // 4 row groups of 32
    const int warp_n = wid >> 2;        // 2 col groups of 64
    const int row0   = blockIdx.x * 128;

    const __nv_bfloat16* Bh = blockIdx.y ? B1h : B0h;
    const __nv_bfloat16* Bl = blockIdx.y ? B1l : B0l;
    float* C = blockIdx.y ? C1 : C0;

    float acc[2][8][4];
    #pragma unroll
    for (int m = 0; m < 2; ++m)
        #pragma unroll
        for (int f = 0; f < 8; ++f)
            #pragma unroll
            for (int q = 0; q < 4; ++q) acc[m][f][q] = 0.f;

    // Precomputed ldmatrix offsets (within a chunk tile)
    // A: row = warp_m*32 + mfrag*16 + (lane&15); colb = ((lane>>4)*8)*2
    const uint32_t a_off0 = SWZ((uint32_t)((warp_m * 32 + (lane & 15)) * 128
                                           + ((lane >> 4) << 3) * 2));
    // B: row = warp_n*64 + p*16 + ((lane>>4)<<3) + (lane&7); colb = ((lane>>3)&1)*8*2
    const uint32_t b_row  = warp_n * 64 + ((lane >> 4) << 3) + (lane & 7);
    const uint32_t b_colb = ((lane >> 3) & 1) * 16;

    constexpr int NC = K / 64;
    for (int c = 0; c < NC; ++c) {
        __syncthreads();   // previous chunk's compute done before overwrite

        // Stage A chunk: 128 rows x 64 cols fp32 -> hi/lo bf16 (swizzled)
        #pragma unroll
        for (int g = tid; g < 1024; g += 256) {
            int row  = g >> 3;
            int j    = g & 7;
            int grow = row0 + row;
            float4 f0 = make_float4(0.f, 0.f, 0.f, 0.f), f1 = f0;
            if (grow < n) {
                const float* ap = A + (size_t)grow * K + c * 64 + j * 8;
                f0 = *(const float4*)ap;
                f1 = *(const float4*)(ap + 4);
            }
            float f[8] = {f0.x, f0.y, f0.z, f0.w, f1.x, f1.y, f1.z, f1.w};
            uint32_t hv[4], lv[4];
            #pragma unroll
            for (int q = 0; q < 4; ++q) {
                __nv_bfloat16 ha = __float2bfloat16(f[2 * q]);
                __nv_bfloat16 hb = __float2bfloat16(f[2 * q + 1]);
                __nv_bfloat162 hp = __halves2bfloat162(ha, hb);
                hv[q] = *reinterpret_cast<uint32_t*>(&hp);
                __nv_bfloat162 lp = __floats2bfloat162_rn(
                    f[2 * q] - __bfloat162float(ha),
                    f[2 * q + 1] - __bfloat162float(hb));
                lv[q] = *reinterpret_cast<uint32_t*>(&lp);
            }
            uint32_t off = SWZ((uint32_t)(row * 128 + j * 16));
            *(uint4*)(smem + AH + off) = make_uint4(hv[0], hv[1], hv[2], hv[3]);
            *(uint4*)(smem + AL + off) = make_uint4(lv[0], lv[1], lv[2], lv[3]);
        }
        // Stage B chunk (hi + lo): 128 rows x 64 cols bf16
        #pragma unroll
        for (int g = tid; g < 1024; g += 256) {
            int row = g >> 3;
            int j   = g & 7;
            const __nv_bfloat16* bp = Bh + (size_t)row * K + c * 64 + j * 8;
            const __nv_bfloat16* lp = Bl + (size_t)row * K + c * 64 + j * 8;
            uint32_t off = SWZ((uint32_t)(row * 128 + j * 16));
            *(uint4*)(smem + BH + off) = *(const uint4*)bp;
            *(uint4*)(smem + BL + off) = *(const uint4*)lp;
        }
        __syncthreads();

        #pragma unroll
        for (int ks = 0; ks < 4; ++ks) {
            // A fragments (hi, lo) for both m16 sub-tiles
            uint32_t ah[2][4], al[2][4];
            #pragma unroll
            for (int m = 0; m < 2; ++m) {
                uint32_t off = a_off0 ^ SWZ((uint32_t)(m * 16 * 128))   // row+16*m
                                 ; // row term is linear in bits>=7; recompute properly:
                off = SWZ((uint32_t)((warp_m * 32 + m * 16 + (lane & 15)) * 128
                                     + (((lane >> 4) << 3) + ks * 16) * 2));
                ldsm_x4(sb + AH + off, ah[m][0], ah[m][1], ah[m][2], ah[m][3]);
                ldsm_x4(sb + AL + off, al[m][0], al[m][1], al[m][2], al[m][3]);
            }
            // B fragment pairs, 3-term split MMA
            #pragma unroll
            for (int p = 0; p < 4; ++p) {
                uint32_t off = SWZ((uint32_t)((b_row + p * 16) * 128
                                              + (ks * 16) * 2 + b_colb));
                uint32_t bh0, bh1, bh2, bh3, bl0, bl1, bl2, bl3;
                ldsm_x4(sb + BH + off, bh0, bh1, bh2, bh3);
                ldsm_x4(sb + BL + off, bl0, bl1, bl2, bl3);
                #pragma unroll
                for (int m = 0; m < 2; ++m) {
                    mma_bf16(acc[m][p * 2 + 0], ah[m], bh0, bh1);
                    mma_bf16(acc[m][p * 2 + 0], ah[m], bl0, bl1);
                    mma_bf16(acc[m][p * 2 + 0], al[m], bh0, bh1);
                    mma_bf16(acc[m][p * 2 + 1], ah[m], bh2, bh3);
                    mma_bf16(acc[m][p * 2 + 1], ah[m], bl2, bl3);
                    mma_bf16(acc[m][p * 2 + 1], al[m], bh2, bh3);
                }
            }
        }
    }

    // Epilogue: write accumulators
    #pragma unroll
    for (int m = 0; m < 2; ++m) {
        int r0 = row0 + warp_m * 32 + m * 16 + (lane >> 2);
        int r1 = r0 + 8;
        #pragma unroll
        for (int f = 0; f < 8; ++f) {
            int col = warp_n * 64 + f * 8 + (lane & 3) * 2;
            if (r0 < n)
                *(float2*)(C + (size_t)r0 * 128 + col) =
                    make_float2(acc[m][f][0], acc[m][f][1]);
            if (r1 < n)
                *(float2*)(C + (size_t)r1 * 128 + col) =
                    make_float2(acc[m][f][2], acc[m][f][3]);
        }
    }
}

// ---------------------------------------------------------------------------
// Fused SpMM + self-add + relu:
//   h[i,:] = relu( s[i,:] + (sum_{j in N(i)} z[j,:]) / (deg[i]+1) )
// ---------------------------------------------------------------------------
__global__ __launch_bounds__(256) void spmm_fused_kernel(
    const float* __restrict__ z, const float* __restrict__ s,
    float* __restrict__ h, int n) {
    int w = (blockIdx.x * blockDim.x + threadIdx.x) >> 5;
    if (w >= n) return;
    int lane = threadIdx.x & 31;
    int st = g_rowptr[w], en = g_rowptr[w + 1];
    float4 acc = make_float4(0.f, 0.f, 0.f, 0.f);
    const float4* zp = (const float4*)z;
    for (int k = st; k < en; ++k) {
        int j = __ldg(&g_csr[k]);
        float4 a = __ldg(&zp[(size_t)j * 32 + lane]);
        acc.x += a.x; acc.y += a.y; acc.z += a.z; acc.w += a.w;
    }
    float inv = 1.0f / (float)(en - st + 1);
    float4 sv = __ldg(&((const float4*)s)[(size_t)w * 32 + lane]);
    float4 o = make_float4(fmaxf(sv.x + acc.x * inv, 0.f),
                           fmaxf(sv.y + acc.y * inv, 0.f),
                           fmaxf(sv.z + acc.z * inv, 0.f),
                           fmaxf(sv.w + acc.w * inv, 0.f));
    ((float4*)h)[(size_t)w * 32 + lane] = o;
}

// ---------------------------------------------------------------------------
// Fused MLP + log_softmax (warp per node).
// ---------------------------------------------------------------------------
#define MLP_NPW 16

__global__ __launch_bounds__(256) void mlp_kernel(const float* __restrict__ h2,
                                                  const float* __restrict__ W,
                                                  const float* __restrict__ bias,
                                                  float* __restrict__ out, int n) {
    __shared__ float Ws[NCLASS * 129];
    const int tid = threadIdx.x;
    for (int i = tid; i < NCLASS * 128; i += 256) {
        int c = i >> 7, k = i & 127;
        Ws[c * 129 + k] = W[i];
    }
    __syncthreads();

    const int lane = tid & 31;
    const int wid  = tid >> 5;
    const int warp_global = blockIdx.x * 8 + wid;
    float b0 = __ldg(&bias[lane]);
    float b1 = (lane < NCLASS - 32) ? __ldg(&bias[lane + 32]) : 0.f;

    for (int it = 0; it < MLP_NPW; ++it) {
        int node = warp_global * MLP_NPW + it;
        if (node >= n) break;
        const float* hr = h2 + (size_t)node * 128;
        float v0 = b0, v1 = b1;
        #pragma unroll 4
        for (int k = 0; k < 128; ++k) {
            float hh = __ldg(&hr[k]);
            v0 = fmaf(hh, Ws[lane * 129 + k], v0);
            if (lane < 8) v1 = fmaf(hh, Ws[(lane + 32) * 129 + k], v1);
        }
        float m = v0;
        if (lane < 8) m = fmaxf(m, v1);
        #pragma unroll
        for (int off = 16; off >= 1; off >>= 1)
            m = fmaxf(m, __shfl_xor_sync(0xffffffffu, m, off));
        float sum = expf(v0 - m) + ((lane < 8) ? expf(v1 - m) : 0.f);
        #pragma unroll
        for (int off = 16; off >= 1; off >>= 1)
            sum += __shfl_xor_sync(0xffffffffu, sum, off);
        float ls = logf(sum);
        float* orow = out + (size_t)node * NCLASS;
        orow[lane] = v0 - m - ls;
        if (lane < 8) orow[32 + lane] = v1 - m - ls;
    }
}

// ---------------------------------------------------------------------------
// Launch
// ---------------------------------------------------------------------------
extern "C" void kernel_launch(void* const* d_in, const int* in_sizes, int n_in,
                              void* d_out, int out_size) {
    const float* x    = (const float*)d_in[0];
    const float* W1   = (const float*)d_in[1];
    const float* W2   = (const float*)d_in[2];
    const float* mlpW = (const float*)d_in[3];
    const float* mlpb = (const float*)d_in[4];
    const int*   rows = (const int*)d_in[5];
    const int*   cols = (const int*)d_in[6];
    const int n = in_sizes[0] / NFEAT;
    const int e = in_sizes[5];
    float* out = (float*)d_out;

    void *p_s, *p_z, *p_h1, *p_h2;
    void *p_b1s_hi, *p_b1s_lo, *p_b1n_hi, *p_b1n_lo;
    void *p_b2s_hi, *p_b2s_lo, *p_b2n_hi, *p_b2n_lo;
    cudaGetSymbolAddress(&p_s, g_s);
    cudaGetSymbolAddress(&p_z, g_z);
    cudaGetSymbolAddress(&p_h1, g_h1);
    cudaGetSymbolAddress(&p_h2, g_h2);
    cudaGetSymbolAddress(&p_b1s_hi, g_b1s_hi);
    cudaGetSymbolAddress(&p_b1s_lo, g_b1s_lo);
    cudaGetSymbolAddress(&p_b1n_hi, g_b1n_hi);
    cudaGetSymbolAddress(&p_b1n_lo, g_b1n_lo);
    cudaGetSymbolAddress(&p_b2s_hi, g_b2s_hi);
    cudaGetSymbolAddress(&p_b2s_lo, g_b2s_lo);
    cudaGetSymbolAddress(&p_b2n_hi, g_b2n_hi);
    cudaGetSymbolAddress(&p_b2n_lo, g_b2n_lo);

    constexpr int SMEM = 65536;   // 4 x 16KB tiles
    cudaFuncSetAttribute(mma_gemm_kernel<256>,
                         cudaFuncAttributeMaxDynamicSharedMemorySize, SMEM);
    cudaFuncSetAttribute(mma_gemm_kernel<128>,
                         cudaFuncAttributeMaxDynamicSharedMemorySize, SMEM);

    // Weight prep
    prep_w1_kernel<<<(128 * 256 + 255) / 256, 256>>>(W1);
    prep_w2_kernel<<<(128 * 128 + 255) / 256, 256>>>(W2);

    // CSR build
    zero_cnt_kernel<<<(n + 255) / 256, 256>>>(n);
    count_kernel<<<(e + 255) / 256, 256>>>(rows, e);
    scan_kernel<<<1, 1024>>>(n, e);
    fill_kernel<<<(e + 255) / 256, 256>>>(rows, cols, e);

    const int gx = (n + 127) / 128;
    const int spmm_blocks = (n * 32 + 255) / 256;

    // Layer 1: s = x @ W1top^T, z = x @ W1bot^T
    mma_gemm_kernel<256><<<dim3(gx, 2), 256, SMEM>>>(
        x,
        (const __nv_bfloat16*)p_b1s_hi, (const __nv_bfloat16*)p_b1s_lo, (float*)p_s,
        (const __nv_bfloat16*)p_b1n_hi, (const __nv_bfloat16*)p_b1n_lo, (float*)p_z,
        n);
    spmm_fused_kernel<<<spmm_blocks, 256>>>((const float*)p_z, (const float*)p_s,
                                            (float*)p_h1, n);

    // Layer 2
    mma_gemm_kernel<128><<<dim3(gx, 2), 256, SMEM>>>(
        (const float*)p_h1,
        (const __nv_bfloat16*)p_b2s_hi, (const __nv_bfloat16*)p_b2s_lo, (float*)p_s,
        (const __nv_bfloat16*)p_b2n_hi, (const __nv_bfloat16*)p_b2n_lo, (float*)p_z,
        n);
    spmm_fused_kernel<<<spmm_blocks, 256>>>((const float*)p_z, (const float*)p_s,
                                            (float*)p_h2, n);

    // MLP + log_softmax
    int mlp_warps  = (n + MLP_NPW - 1) / MLP_NPW;
    int mlp_blocks = (mlp_warps + 7) / 8;
    mlp_kernel<<<mlp_blocks, 256>>>((const float*)p_h2, mlpW, mlpb, out, n);
}

// round 7
// speedup vs baseline: 1.7791x; 1.1450x over previous
#include <cuda_runtime.h>
#include <cuda_bf16.h>
#include <cuda_fp16.h>
#include <math.h>
#include <stdint.h>

// Problem constants
#define NFEAT   256
#define NHID    128
#define NCLASS  40
#define MAXN    100000
#define MAXE    3200000
#define NPAD    (MAXN + 128)   // rows padded so cp.async tail reads stay in-bounds

// ---------------------------------------------------------------------------
// Static device scratch
// ---------------------------------------------------------------------------
__device__ int   g_cnt[MAXN];
__device__ int   g_rowptr[MAXN + 1];
__device__ int   g_next[MAXN];
__device__ int   g_csr[MAXE];
__device__ float  g_s[(size_t)MAXN * NHID];          // self-projection (fp32)
__device__ __half g_z[(size_t)MAXN * NHID];          // neigh-projection (fp16)
__device__ __nv_bfloat16 g_h1_hi[(size_t)NPAD * NHID];  // h1 pre-split for GEMM2
__device__ __nv_bfloat16 g_h1_lo[(size_t)NPAD * NHID];
__device__ float g_h2[(size_t)MAXN * NHID];
// bf16-split weights, [128 out-rows, K in-cols] K-major
__device__ __nv_bfloat16 g_b1s_hi[128 * 256], g_b1s_lo[128 * 256];
__device__ __nv_bfloat16 g_b1n_hi[128 * 256], g_b1n_lo[128 * 256];
__device__ __nv_bfloat16 g_b2s_hi[128 * 128], g_b2s_lo[128 * 128];
__device__ __nv_bfloat16 g_b2n_hi[128 * 128], g_b2n_lo[128 * 128];

// ---------------------------------------------------------------------------
// Helpers
// ---------------------------------------------------------------------------
__device__ __forceinline__ uint32_t smem_u32(const void* p) {
    uint32_t a;
    asm("{ .reg .u64 t; cvta.to.shared.u64 t, %1; cvt.u32.u64 %0, t; }"
        : "=r"(a) : "l"(p));
    return a;
}

#define SWZ(x) ((x) ^ (((x) >> 3) & 0x70))

__device__ __forceinline__ void ldsm_x4(uint32_t addr, uint32_t& r0, uint32_t& r1,
                                        uint32_t& r2, uint32_t& r3) {
    asm volatile("ldmatrix.sync.aligned.m8n8.x4.shared.b16 {%0,%1,%2,%3}, [%4];"
                 : "=r"(r0), "=r"(r1), "=r"(r2), "=r"(r3) : "r"(addr));
}

__device__ __forceinline__ void mma_bf16(float* d, const uint32_t* a,
                                         uint32_t b0, uint32_t b1) {
    asm volatile(
        "mma.sync.aligned.m16n8k16.row.col.f32.bf16.bf16.f32 "
        "{%0,%1,%2,%3}, {%4,%5,%6,%7}, {%8,%9}, {%0,%1,%2,%3};"
        : "+f"(d[0]), "+f"(d[1]), "+f"(d[2]), "+f"(d[3])
        : "r"(a[0]), "r"(a[1]), "r"(a[2]), "r"(a[3]), "r"(b0), "r"(b1));
}

__device__ __forceinline__ void cp16(uint32_t dst, const void* src) {
    asm volatile("cp.async.cg.shared.global [%0], [%1], 16;"
                 :: "r"(dst), "l"(src));
}
#define CP_COMMIT() asm volatile("cp.async.commit_group;" ::: "memory")
#define CP_WAIT0()  asm volatile("cp.async.wait_group 0;" ::: "memory")

// ---------------------------------------------------------------------------
// CSR build
// ---------------------------------------------------------------------------
__global__ void zero_cnt_kernel(int n) {
    int i = blockIdx.x * blockDim.x + threadIdx.x;
    if (i < n) g_cnt[i] = 0;
}

__global__ void count_kernel(const int* __restrict__ rows, int e) {
    int i = blockIdx.x * blockDim.x + threadIdx.x;
    if (i < e) atomicAdd(&g_cnt[rows[i]], 1);
}

__global__ void scan_kernel(int n, int etot) {
    __shared__ int wsum[32];
    __shared__ int carry_s;
    const int tid  = threadIdx.x;
    const int lane = tid & 31;
    const int wid  = tid >> 5;
    if (tid == 0) carry_s = 0;
    __syncthreads();

    for (int base = 0; base < n; base += 1024) {
        int i = base + tid;
        int v = (i < n) ? g_cnt[i] : 0;
        int incl = v;
        #pragma unroll
        for (int off = 1; off < 32; off <<= 1) {
            int t = __shfl_up_sync(0xffffffffu, incl, off);
            if (lane >= off) incl += t;
        }
        if (lane == 31) wsum[wid] = incl;
        __syncthreads();
        if (wid == 0) {
            int s  = wsum[lane];
            int si = s;
            #pragma unroll
            for (int off = 1; off < 32; off <<= 1) {
                int t = __shfl_up_sync(0xffffffffu, si, off);
                if (lane >= off) si += t;
            }
            wsum[lane] = si - s;
        }
        __syncthreads();
        int c    = carry_s;
        int excl = c + wsum[wid] + (incl - v);
        if (i < n) { g_rowptr[i] = excl; g_next[i] = excl; }
        __syncthreads();
        if (tid == 1023) carry_s = c + wsum[31] + incl;
        __syncthreads();
    }
    if (tid == 0) g_rowptr[n] = etot;
}

__global__ void fill_kernel(const int* __restrict__ rows,
                            const int* __restrict__ cols, int e) {
    int i = blockIdx.x * blockDim.x + threadIdx.x;
    if (i < e) {
        int p = atomicAdd(&g_next[rows[i]], 1);
        g_csr[p] = cols[i];
    }
}

// ---------------------------------------------------------------------------
// Weight prep: split fp32 -> (hi, lo) bf16, slicing concat halves.
// ---------------------------------------------------------------------------
__global__ void prep_w1_kernel(const float* __restrict__ W1) {
    int idx = blockIdx.x * blockDim.x + threadIdx.x;
    if (idx >= 128 * 256) return;
    int j = idx >> 8, k = idx & 255;
    float a = W1[j * 512 + k];
    __nv_bfloat16 ha = __float2bfloat16(a);
    g_b1s_hi[idx] = ha;
    g_b1s_lo[idx] = __float2bfloat16(a - __bfloat162float(ha));
    float b = W1[j * 512 + 256 + k];
    __nv_bfloat16 hb = __float2bfloat16(b);
    g_b1n_hi[idx] = hb;
    g_b1n_lo[idx] = __float2bfloat16(b - __bfloat162float(hb));
}

__global__ void prep_w2_kernel(const float* __restrict__ W2) {
    int idx = blockIdx.x * blockDim.x + threadIdx.x;
    if (idx >= 128 * 128) return;
    int j = idx >> 7, k = idx & 127;
    float a = W2[j * 256 + k];
    __nv_bfloat16 ha = __float2bfloat16(a);
    g_b2s_hi[idx] = ha;
    g_b2s_lo[idx] = __float2bfloat16(a - __bfloat162float(ha));
    float b = W2[j * 256 + 128 + k];
    __nv_bfloat16 hb = __float2bfloat16(b);
    g_b2n_hi[idx] = hb;
    g_b2n_lo[idx] = __float2bfloat16(b - __bfloat162float(hb));
}

// ---------------------------------------------------------------------------
// Merged double-buffered GEMM (bf16 split-3, mma.sync):
//   s[blk,128] = A @ Bs^T (fp32 out),  z[blk,128] = A @ Bn^T (fp16 out)
// Block 128 rows x 256 out-cols, 512 threads = 16 warps (4 M x 4 N of 32x64).
// warp_n 0,1 -> s cols; warp_n 2,3 -> z cols. K chunked by 64, 2 smem buffers.
// ASPLIT=false: A fp32, converted on the fly (register-prefetched).
// ASPLIT=true:  A pre-split bf16 hi/lo, staged via cp.async.
// ---------------------------------------------------------------------------
template <int K, bool ASPLIT>
__global__ __launch_bounds__(512, 1) void mma_gemm_kernel(
    const float* __restrict__ A,
    const __nv_bfloat16* __restrict__ Ah, const __nv_bfloat16* __restrict__ Al,
    const __nv_bfloat16* __restrict__ Bsh, const __nv_bfloat16* __restrict__ Bsl,
    const __nv_bfloat16* __restrict__ Bnh, const __nv_bfloat16* __restrict__ Bnl,
    float* __restrict__ Cs, __half* __restrict__ Cz, int n) {
    extern __shared__ char smem[];
    constexpr int BUF  = 98304;          // per-buffer bytes
    constexpr int AOFF = 0;              // A_hi 16K, A_lo 16K
    constexpr int BOFF = 32768;          // 4 B tiles x 16K (sh, sl, nh, nl)
    constexpr int NC   = K / 64;
    const uint32_t sb = smem_u32(smem);
    const int tid    = threadIdx.x;
    const int lane   = tid & 31;
    const int wid    = tid >> 5;
    const int warp_m = wid & 3;
    const int warp_n = wid >> 2;         // 0..3
    const int row0   = blockIdx.x * 128;

    float acc[2][8][4];
    #pragma unroll
    for (int m = 0; m < 2; ++m)
        #pragma unroll
        for (int f = 0; f < 8; ++f)
            #pragma unroll
            for (int q = 0; q < 4; ++q) acc[m][f][q] = 0.f;

    // ---- staging lambdas (macro-style) ----
    auto stage_B = [&](int c, int buf) {
        #pragma unroll
        for (int t = 0; t < 4; ++t) {
            const __nv_bfloat16* B = (t == 0) ? Bsh : (t == 1) ? Bsl
                                   : (t == 2) ? Bnh : Bnl;
            #pragma unroll
            for (int i = tid; i < 1024; i += 512) {
                int row = i >> 3, j = i & 7;
                cp16(sb + buf * BUF + BOFF + t * 16384 + SWZ((uint32_t)(row * 128 + j * 16)),
                     B + (size_t)row * K + c * 64 + j * 8);
            }
        }
    };
    auto stage_A_async = [&](int c, int buf) {
        #pragma unroll
        for (int t = 0; t < 2; ++t) {
            const __nv_bfloat16* Ap = t ? Al : Ah;
            #pragma unroll
            for (int i = tid; i < 1024; i += 512) {
                int row = i >> 3, j = i & 7;
                cp16(sb + buf * BUF + AOFF + t * 16384 + SWZ((uint32_t)(row * 128 + j * 16)),
                     Ap + (size_t)(row0 + row) * K + c * 64 + j * 8);
            }
        }
    };
    float ar[2][8];
    auto load_A_regs = [&](int c) {
        #pragma unroll
        for (int t = 0; t < 2; ++t) {
            int g = tid + t * 512;
            int row = g >> 3, j = g & 7;
            int grow = row0 + row;
            float4 f0 = make_float4(0.f, 0.f, 0.f, 0.f), f1 = f0;
            if (grow < n) {
                const float* ap = A + (size_t)grow * K + c * 64 + j * 8;
                f0 = *(const float4*)ap;
                f1 = *(const float4*)(ap + 4);
            }
            ar[t][0] = f0.x; ar[t][1] = f0.y; ar[t][2] = f0.z; ar[t][3] = f0.w;
            ar[t][4] = f1.x; ar[t][5] = f1.y; ar[t][6] = f1.z; ar[t][7] = f1.w;
        }
    };
    auto convert_store_A = [&](int buf) {
        #pragma unroll
        for (int t = 0; t < 2; ++t) {
            int g = tid + t * 512;
            int row = g >> 3, j = g & 7;
            uint32_t hv[4], lv[4];
            #pragma unroll
            for (int q = 0; q < 4; ++q) {
                float fa = ar[t][2 * q], fb = ar[t][2 * q + 1];
                __nv_bfloat16 ha = __float2bfloat16(fa);
                __nv_bfloat16 hb = __float2bfloat16(fb);
                __nv_bfloat162 hp = __halves2bfloat162(ha, hb);
                hv[q] = *reinterpret_cast<uint32_t*>(&hp);
                __nv_bfloat162 lp = __floats2bfloat162_rn(
                    fa - __bfloat162float(ha), fb - __bfloat162float(hb));
                lv[q] = *reinterpret_cast<uint32_t*>(&lp);
            }
            uint32_t off = SWZ((uint32_t)(row * 128 + j * 16));
            *(uint4*)(smem + buf * BUF + AOFF + off)         = make_uint4(hv[0], hv[1], hv[2], hv[3]);
            *(uint4*)(smem + buf * BUF + AOFF + 16384 + off) = make_uint4(lv[0], lv[1], lv[2], lv[3]);
        }
    };

    // warp-level B addressing
    const uint32_t b_tile_hi = BOFF + ((warp_n >> 1) * 2) * 16384;  // sh or nh
    const int b_row_base = (warp_n & 1) * 64 + ((lane >> 4) << 3) + (lane & 7);
    const uint32_t b_colb = ((lane >> 3) & 1) * 16;

    // ---- prologue: chunk 0 ----
    stage_B(0, 0);
    if (ASPLIT) {
        stage_A_async(0, 0);
        CP_COMMIT();
    } else {
        CP_COMMIT();
        load_A_regs(0);
        convert_store_A(0);
    }
    CP_WAIT0();
    __syncthreads();

    // ---- main loop ----
    for (int c = 0; c < NC; ++c) {
        const int buf = c & 1, nb = buf ^ 1;
        const bool has_next = (c + 1 < NC);
        if (has_next) {
            stage_B(c + 1, nb);
            if (ASPLIT) stage_A_async(c + 1, nb);
            CP_COMMIT();
            if (!ASPLIT) load_A_regs(c + 1);
        }

        const uint32_t abase = sb + buf * BUF + AOFF;
        const uint32_t bbase_h = sb + buf * BUF + b_tile_hi;
        #pragma unroll
        for (int ks = 0; ks < 4; ++ks) {
            uint32_t ahf[2][4], alf[2][4];
            #pragma unroll
            for (int m = 0; m < 2; ++m) {
                uint32_t off = SWZ((uint32_t)((warp_m * 32 + m * 16 + (lane & 15)) * 128
                                              + (((lane >> 4) << 3) + ks * 16) * 2));
                ldsm_x4(abase + off,         ahf[m][0], ahf[m][1], ahf[m][2], ahf[m][3]);
                ldsm_x4(abase + 16384 + off, alf[m][0], alf[m][1], alf[m][2], alf[m][3]);
            }
            #pragma unroll
            for (int p = 0; p < 4; ++p) {
                uint32_t off = SWZ((uint32_t)((b_row_base + p * 16) * 128
                                              + ks * 32 + b_colb));
                uint32_t bh0, bh1, bh2, bh3, bl0, bl1, bl2, bl3;
                ldsm_x4(bbase_h + off,         bh0, bh1, bh2, bh3);
                ldsm_x4(bbase_h + 16384 + off, bl0, bl1, bl2, bl3);
                #pragma unroll
                for (int m = 0; m < 2; ++m) {
                    mma_bf16(acc[m][p * 2 + 0], ahf[m], bh0, bh1);
                    mma_bf16(acc[m][p * 2 + 0], ahf[m], bl0, bl1);
                    mma_bf16(acc[m][p * 2 + 0], alf[m], bh0, bh1);
                    mma_bf16(acc[m][p * 2 + 1], ahf[m], bh2, bh3);
                    mma_bf16(acc[m][p * 2 + 1], ahf[m], bl2, bl3);
                    mma_bf16(acc[m][p * 2 + 1], alf[m], bh2, bh3);
                }
            }
        }

        if (has_next) {
            if (!ASPLIT) convert_store_A(nb);
            CP_WAIT0();
        }
        __syncthreads();
    }

    // ---- epilogue ----
    const bool is_z = warp_n >= 2;
    const int coln0 = (warp_n & 1) * 64;
    #pragma unroll
    for (int m = 0; m < 2; ++m) {
        int r0 = row0 + warp_m * 32 + m * 16 + (lane >> 2);
        int r1 = r0 + 8;
        #pragma unroll
        for (int f = 0; f < 8; ++f) {
            int col = coln0 + f * 8 + (lane & 3) * 2;
            if (is_z) {
                if (r0 < n)
                    *(__half2*)(Cz + (size_t)r0 * 128 + col) =
                        __floats2half2_rn(acc[m][f][0], acc[m][f][1]);
                if (r1 < n)
                    *(__half2*)(Cz + (size_t)r1 * 128 + col) =
                        __floats2half2_rn(acc[m][f][2], acc[m][f][3]);
            } else {
                if (r0 < n)
                    *(float2*)(Cs + (size_t)r0 * 128 + col) =
                        make_float2(acc[m][f][0], acc[m][f][1]);
                if (r1 < n)
                    *(float2*)(Cs + (size_t)r1 * 128 + col) =
                        make_float2(acc[m][f][2], acc[m][f][3]);
            }
        }
    }
}

// ---------------------------------------------------------------------------
// Fused SpMM + self-add + relu over fp16 z:
//   o[i,:] = relu( s[i,:] + (sum_{j in N(i)} z[j,:]) / (deg[i]+1) )
// SPLIT_OUT: write bf16 hi/lo pair (feeds GEMM2); else fp32 (feeds MLP).
// Warp per node; lane owns features [4*lane, 4*lane+4).
// ---------------------------------------------------------------------------
template <bool SPLIT_OUT>
__global__ __launch_bounds__(256) void spmm_fused_kernel(
    const __half* __restrict__ z, const float* __restrict__ s,
    float* __restrict__ h,
    __nv_bfloat16* __restrict__ hhi, __nv_bfloat16* __restrict__ hlo, int n) {
    int w = (blockIdx.x * blockDim.x + threadIdx.x) >> 5;
    if (w >= n) return;
    int lane = threadIdx.x & 31;
    int st = g_rowptr[w], en = g_rowptr[w + 1];
    float a0 = 0.f, a1 = 0.f, a2 = 0.f, a3 = 0.f;
    const uint2* zp = (const uint2*)z;   // 32 x uint2 per row
    int k = st;
    for (; k + 1 < en; k += 2) {
        int j0 = __ldg(&g_csr[k]);
        int j1 = __ldg(&g_csr[k + 1]);
        uint2 u0 = __ldg(&zp[(size_t)j0 * 32 + lane]);
        uint2 u1 = __ldg(&zp[(size_t)j1 * 32 + lane]);
        float2 f0 = __half22float2(*(const __half2*)&u0.x);
        float2 f1 = __half22float2(*(const __half2*)&u0.y);
        float2 f2 = __half22float2(*(const __half2*)&u1.x);
        float2 f3 = __half22float2(*(const __half2*)&u1.y);
        a0 += f0.x + f2.x; a1 += f0.y + f2.y;
        a2 += f1.x + f3.x; a3 += f1.y + f3.y;
    }
    if (k < en) {
        int j0 = __ldg(&g_csr[k]);
        uint2 u0 = __ldg(&zp[(size_t)j0 * 32 + lane]);
        float2 f0 = __half22float2(*(const __half2*)&u0.x);
        float2 f1 = __half22float2(*(const __half2*)&u0.y);
        a0 += f0.x; a1 += f0.y; a2 += f1.x; a3 += f1.y;
    }
    float inv = 1.0f / (float)(en - st + 1);
    float4 sv = __ldg(&((const float4*)s)[(size_t)w * 32 + lane]);
    float o0 = fmaxf(sv.x + a0 * inv, 0.f);
    float o1 = fmaxf(sv.y + a1 * inv, 0.f);
    float o2 = fmaxf(sv.z + a2 * inv, 0.f);
    float o3 = fmaxf(sv.w + a3 * inv, 0.f);
    if (SPLIT_OUT) {
        __nv_bfloat16 h0 = __float2bfloat16(o0), h1 = __float2bfloat16(o1);
        __nv_bfloat16 h2 = __float2bfloat16(o2), h3 = __float2bfloat16(o3);
        __nv_bfloat162 hp0 = __halves2bfloat162(h0, h1);
        __nv_bfloat162 hp1 = __halves2bfloat162(h2, h3);
        ((uint2*)hhi)[(size_t)w * 32 + lane] =
            make_uint2(*reinterpret_cast<uint32_t*>(&hp0),
                       *reinterpret_cast<uint32_t*>(&hp1));
        __nv_bfloat162 lp0 = __floats2bfloat162_rn(o0 - __bfloat162float(h0),
                                                   o1 - __bfloat162float(h1));
        __nv_bfloat162 lp1 = __floats2bfloat162_rn(o2 - __bfloat162float(h2),
                                                   o3 - __bfloat162float(h3));
        ((uint2*)hlo)[(size_t)w * 32 + lane] =
            make_uint2(*reinterpret_cast<uint32_t*>(&lp0),
                       *reinterpret_cast<uint32_t*>(&lp1));
    } else {
        ((float4*)h)[(size_t)w * 32 + lane] = make_float4(o0, o1, o2, o3);
    }
}

// ---------------------------------------------------------------------------
// Fused MLP + log_softmax (warp per node).
// ---------------------------------------------------------------------------
#define MLP_NPW 16

__global__ __launch_bounds__(256) void mlp_kernel(const float* __restrict__ h2,
                                                  const float* __restrict__ W,
                                                  const float* __restrict__ bias,
                                                  float* __restrict__ out, int n) {
    __shared__ float Ws[NCLASS * 129];
    const int tid = threadIdx.x;
    for (int i = tid; i < NCLASS * 128; i += 256) {
        int c = i >> 7, k = i & 127;
        Ws[c * 129 + k] = W[i];
    }
    __syncthreads();

    const int lane = tid & 31;
    const int wid  = tid >> 5;
    const int warp_global = blockIdx.x * 8 + wid;
    float b0 = __ldg(&bias[lane]);
    float b1 = (lane < NCLASS - 32) ? __ldg(&bias[lane + 32]) : 0.f;

    for (int it = 0; it < MLP_NPW; ++it) {
        int node = warp_global * MLP_NPW + it;
        if (node >= n) break;
        const float* hr = h2 + (size_t)node * 128;
        float v0 = b0, v1 = b1;
        #pragma unroll 4
        for (int k = 0; k < 128; ++k) {
            float hh = __ldg(&hr[k]);
            v0 = fmaf(hh, Ws[lane * 129 + k], v0);
            if (lane < 8) v1 = fmaf(hh, Ws[(lane + 32) * 129 + k], v1);
        }
        float m = v0;
        if (lane < 8) m = fmaxf(m, v1);
        #pragma unroll
        for (int off = 16; off >= 1; off >>= 1)
            m = fmaxf(m, __shfl_xor_sync(0xffffffffu, m, off));
        float sum = expf(v0 - m) + ((lane < 8) ? expf(v1 - m) : 0.f);
        #pragma unroll
        for (int off = 16; off >= 1; off >>= 1)
            sum += __shfl_xor_sync(0xffffffffu, sum, off);
        float ls = logf(sum);
        float* orow = out + (size_t)node * NCLASS;
        orow[lane] = v0 - m - ls;
        if (lane < 8) orow[32 + lane] = v1 - m - ls;
    }
}

// ---------------------------------------------------------------------------
// Launch
// ---------------------------------------------------------------------------
extern "C" void kernel_launch(void* const* d_in, const int* in_sizes, int n_in,
                              void* d_out, int out_size) {
    const float* x    = (const float*)d_in[0];
    const float* W1   = (const float*)d_in[1];
    const float* W2   = (const float*)d_in[2];
    const float* mlpW = (const float*)d_in[3];
    const float* mlpb = (const float*)d_in[4];
    const int*   rows = (const int*)d_in[5];
    const int*   cols = (const int*)d_in[6];
    const int n = in_sizes[0] / NFEAT;
    const int e = in_sizes[5];
    float* out = (float*)d_out;

    void *p_s, *p_z, *p_h1h, *p_h1l, *p_h2;
    void *p_b1s_hi, *p_b1s_lo, *p_b1n_hi, *p_b1n_lo;
    void *p_b2s_hi, *p_b2s_lo, *p_b2n_hi, *p_b2n_lo;
    cudaGetSymbolAddress(&p_s, g_s);
    cudaGetSymbolAddress(&p_z, g_z);
    cudaGetSymbolAddress(&p_h1h, g_h1_hi);
    cudaGetSymbolAddress(&p_h1l, g_h1_lo);
    cudaGetSymbolAddress(&p_h2, g_h2);
    cudaGetSymbolAddress(&p_b1s_hi, g_b1s_hi);
    cudaGetSymbolAddress(&p_b1s_lo, g_b1s_lo);
    cudaGetSymbolAddress(&p_b1n_hi, g_b1n_hi);
    cudaGetSymbolAddress(&p_b1n_lo, g_b1n_lo);
    cudaGetSymbolAddress(&p_b2s_hi, g_b2s_hi);
    cudaGetSymbolAddress(&p_b2s_lo, g_b2s_lo);
    cudaGetSymbolAddress(&p_b2n_hi, g_b2n_hi);
    cudaGetSymbolAddress(&p_b2n_lo, g_b2n_lo);

    constexpr int SMEM = 2 * 98304;   // 192 KB double buffer
    cudaFuncSetAttribute(mma_gemm_kernel<256, false>,
                         cudaFuncAttributeMaxDynamicSharedMemorySize, SMEM);
    cudaFuncSetAttribute(mma_gemm_kernel<128, true>,
                         cudaFuncAttributeMaxDynamicSharedMemorySize, SMEM);

    // Weight prep
    prep_w1_kernel<<<(128 * 256 + 255) / 256, 256>>>(W1);
    prep_w2_kernel<<<(128 * 128 + 255) / 256, 256>>>(W2);

    // CSR build
    zero_cnt_kernel<<<(n + 255) / 256, 256>>>(n);
    count_kernel<<<(e + 255) / 256, 256>>>(rows, e);
    scan_kernel<<<1, 1024>>>(n, e);
    fill_kernel<<<(e + 255) / 256, 256>>>(rows, cols, e);

    const int gx = (n + 127) / 128;
    const int spmm_blocks = (n * 32 + 255) / 256;

    // Layer 1: s = x@W1top^T (fp32), z = x@W1bot^T (fp16), one pass over x
    mma_gemm_kernel<256, false><<<gx, 512, SMEM>>>(
        x, nullptr, nullptr,
        (const __nv_bfloat16*)p_b1s_hi, (const __nv_bfloat16*)p_b1s_lo,
        (const __nv_bfloat16*)p_b1n_hi, (const __nv_bfloat16*)p_b1n_lo,
        (float*)p_s, (__half*)p_z, n);
    spmm_fused_kernel<true><<<spmm_blocks, 256>>>(
        (const __half*)p_z, (const float*)p_s, nullptr,
        (__nv_bfloat16*)p_h1h, (__nv_bfloat16*)p_h1l, n);

    // Layer 2: A pre-split bf16 (pure cp.async path)
    mma_gemm_kernel<128, true><<<gx, 512, SMEM>>>(
        nullptr, (const __nv_bfloat16*)p_h1h, (const __nv_bfloat16*)p_h1l,
        (const __nv_bfloat16*)p_b2s_hi, (const __nv_bfloat16*)p_b2s_lo,
        (const __nv_bfloat16*)p_b2n_hi, (const __nv_bfloat16*)p_b2n_lo,
        (float*)p_s, (__half*)p_z, n);
    spmm_fused_kernel<false><<<spmm_blocks, 256>>>(
        (const __half*)p_z, (const float*)p_s, (float*)p_h2,
        nullptr, nullptr, n);

    // MLP + log_softmax
    int mlp_warps  = (n + MLP_NPW - 1) / MLP_NPW;
    int mlp_blocks = (mlp_warps + 7) / 8;
    mlp_kernel<<<mlp_blocks, 256>>>((const float*)p_h2, mlpW, mlpb, out, n);
}

// round 8
// speedup vs baseline: 2.0492x; 1.1519x over previous
#include <cuda_runtime.h>
#include <cuda_bf16.h>
#include <cuda_fp16.h>
#include <math.h>
#include <stdint.h>

// Problem constants
#define NFEAT   256
#define NHID    128
#define NCLASS  40
#define MAXN    100000
#define MAXE    3200000
#define NPAD    (MAXN + 128)   // rows padded so cp.async tail reads stay in-bounds

// ---------------------------------------------------------------------------
// Static device scratch
// ---------------------------------------------------------------------------
__device__ int   g_cnt[MAXN];
__device__ int   g_rowptr[MAXN + 1];
__device__ int   g_next[MAXN];
__device__ int   g_csr[MAXE];
__device__ float  g_s[(size_t)MAXN * NHID];          // self-projection (fp32)
__device__ __half g_z[(size_t)MAXN * NHID];          // neigh-projection (fp16)
__device__ __nv_bfloat16 g_h1_hi[(size_t)NPAD * NHID];  // h1 pre-split for GEMM2
__device__ __nv_bfloat16 g_h1_lo[(size_t)NPAD * NHID];
// bf16-split weights, [128 out-rows, K in-cols] K-major
__device__ __nv_bfloat16 g_b1s_hi[128 * 256], g_b1s_lo[128 * 256];
__device__ __nv_bfloat16 g_b1n_hi[128 * 256], g_b1n_lo[128 * 256];
__device__ __nv_bfloat16 g_b2s_hi[128 * 128], g_b2s_lo[128 * 128];
__device__ __nv_bfloat16 g_b2n_hi[128 * 128], g_b2n_lo[128 * 128];

// ---------------------------------------------------------------------------
// Helpers
// ---------------------------------------------------------------------------
__device__ __forceinline__ uint32_t smem_u32(const void* p) {
    uint32_t a;
    asm("{ .reg .u64 t; cvta.to.shared.u64 t, %1; cvt.u32.u64 %0, t; }"
        : "=r"(a) : "l"(p));
    return a;
}

#define SWZ(x) ((x) ^ (((x) >> 3) & 0x70))

__device__ __forceinline__ void ldsm_x4(uint32_t addr, uint32_t& r0, uint32_t& r1,
                                        uint32_t& r2, uint32_t& r3) {
    asm volatile("ldmatrix.sync.aligned.m8n8.x4.shared.b16 {%0,%1,%2,%3}, [%4];"
                 : "=r"(r0), "=r"(r1), "=r"(r2), "=r"(r3) : "r"(addr));
}

__device__ __forceinline__ void mma_bf16(float* d, const uint32_t* a,
                                         uint32_t b0, uint32_t b1) {
    asm volatile(
        "mma.sync.aligned.m16n8k16.row.col.f32.bf16.bf16.f32 "
        "{%0,%1,%2,%3}, {%4,%5,%6,%7}, {%8,%9}, {%0,%1,%2,%3};"
        : "+f"(d[0]), "+f"(d[1]), "+f"(d[2]), "+f"(d[3])
        : "r"(a[0]), "r"(a[1]), "r"(a[2]), "r"(a[3]), "r"(b0), "r"(b1));
}

__device__ __forceinline__ void cp16(uint32_t dst, const void* src) {
    asm volatile("cp.async.cg.shared.global [%0], [%1], 16;"
                 :: "r"(dst), "l"(src));
}
#define CP_COMMIT() asm volatile("cp.async.commit_group;" ::: "memory")
#define CP_WAIT0()  asm volatile("cp.async.wait_group 0;" ::: "memory")

// ---------------------------------------------------------------------------
// Merged prep: W1 split (idx<32768), W2 split (idx<16384), zero g_cnt (idx<n)
// ---------------------------------------------------------------------------
__global__ void prep_kernel(const float* __restrict__ W1,
                            const float* __restrict__ W2, int n) {
    int idx = blockIdx.x * blockDim.x + threadIdx.x;
    if (idx < 128 * 256) {
        int j = idx >> 8, k = idx & 255;
        float a = W1[j * 512 + k];
        __nv_bfloat16 ha = __float2bfloat16(a);
        g_b1s_hi[idx] = ha;
        g_b1s_lo[idx] = __float2bfloat16(a - __bfloat162float(ha));
        float b = W1[j * 512 + 256 + k];
        __nv_bfloat16 hb = __float2bfloat16(b);
        g_b1n_hi[idx] = hb;
        g_b1n_lo[idx] = __float2bfloat16(b - __bfloat162float(hb));
    }
    if (idx < 128 * 128) {
        int j = idx >> 7, k = idx & 127;
        float a = W2[j * 256 + k];
        __nv_bfloat16 ha = __float2bfloat16(a);
        g_b2s_hi[idx] = ha;
        g_b2s_lo[idx] = __float2bfloat16(a - __bfloat162float(ha));
        float b = W2[j * 256 + 128 + k];
        __nv_bfloat16 hb = __float2bfloat16(b);
        g_b2n_hi[idx] = hb;
        g_b2n_lo[idx] = __float2bfloat16(b - __bfloat162float(hb));
    }
    if (idx < n) g_cnt[idx] = 0;
}

// ---------------------------------------------------------------------------
// CSR build
// ---------------------------------------------------------------------------
__global__ void count_kernel(const int* __restrict__ rows, int e) {
    int i = blockIdx.x * blockDim.x + threadIdx.x;
    if (i < e) atomicAdd(&g_cnt[rows[i]], 1);
}

__global__ void scan_kernel(int n, int etot) {
    __shared__ int wsum[32];
    __shared__ int carry_s;
    const int tid  = threadIdx.x;
    const int lane = tid & 31;
    const int wid  = tid >> 5;
    if (tid == 0) carry_s = 0;
    __syncthreads();

    for (int base = 0; base < n; base += 1024) {
        int i = base + tid;
        int v = (i < n) ? g_cnt[i] : 0;
        int incl = v;
        #pragma unroll
        for (int off = 1; off < 32; off <<= 1) {
            int t = __shfl_up_sync(0xffffffffu, incl, off);
            if (lane >= off) incl += t;
        }
        if (lane == 31) wsum[wid] = incl;
        __syncthreads();
        if (wid == 0) {
            int s  = wsum[lane];
            int si = s;
            #pragma unroll
            for (int off = 1; off < 32; off <<= 1) {
                int t = __shfl_up_sync(0xffffffffu, si, off);
                if (lane >= off) si += t;
            }
            wsum[lane] = si - s;
        }
        __syncthreads();
        int c    = carry_s;
        int excl = c + wsum[wid] + (incl - v);
        if (i < n) { g_rowptr[i] = excl; g_next[i] = excl; }
        __syncthreads();
        if (tid == 1023) carry_s = c + wsum[31] + incl;
        __syncthreads();
    }
    if (tid == 0) g_rowptr[n] = etot;
}

__global__ void fill_kernel(const int* __restrict__ rows,
                            const int* __restrict__ cols, int e) {
    int i = blockIdx.x * blockDim.x + threadIdx.x;
    if (i < e) {
        int p = atomicAdd(&g_next[rows[i]], 1);
        g_csr[p] = cols[i];
    }
}

// ---------------------------------------------------------------------------
// Merged double-buffered GEMM (bf16 split-3, mma.sync):
//   s[blk,128] = A @ Bs^T (fp32 out),  z[blk,128] = A @ Bn^T (fp16 out)
// Block 128 rows x 256 out-cols, 512 threads = 16 warps (4 M x 4 N of 32x64).
// ---------------------------------------------------------------------------
template <int K, bool ASPLIT>
__global__ __launch_bounds__(512, 1) void mma_gemm_kernel(
    const float* __restrict__ A,
    const __nv_bfloat16* __restrict__ Ah, const __nv_bfloat16* __restrict__ Al,
    const __nv_bfloat16* __restrict__ Bsh, const __nv_bfloat16* __restrict__ Bsl,
    const __nv_bfloat16* __restrict__ Bnh, const __nv_bfloat16* __restrict__ Bnl,
    float* __restrict__ Cs, __half* __restrict__ Cz, int n) {
    extern __shared__ char smem[];
    constexpr int BUF  = 98304;
    constexpr int AOFF = 0;
    constexpr int BOFF = 32768;
    constexpr int NC   = K / 64;
    const uint32_t sb = smem_u32(smem);
    const int tid    = threadIdx.x;
    const int lane   = tid & 31;
    const int wid    = tid >> 5;
    const int warp_m = wid & 3;
    const int warp_n = wid >> 2;
    const int row0   = blockIdx.x * 128;

    float acc[2][8][4];
    #pragma unroll
    for (int m = 0; m < 2; ++m)
        #pragma unroll
        for (int f = 0; f < 8; ++f)
            #pragma unroll
            for (int q = 0; q < 4; ++q) acc[m][f][q] = 0.f;

    auto stage_B = [&](int c, int buf) {
        #pragma unroll
        for (int t = 0; t < 4; ++t) {
            const __nv_bfloat16* B = (t == 0) ? Bsh : (t == 1) ? Bsl
                                   : (t == 2) ? Bnh : Bnl;
            #pragma unroll
            for (int i = tid; i < 1024; i += 512) {
                int row = i >> 3, j = i & 7;
                cp16(sb + buf * BUF + BOFF + t * 16384 + SWZ((uint32_t)(row * 128 + j * 16)),
                     B + (size_t)row * K + c * 64 + j * 8);
            }
        }
    };
    auto stage_A_async = [&](int c, int buf) {
        #pragma unroll
        for (int t = 0; t < 2; ++t) {
            const __nv_bfloat16* Ap = t ? Al : Ah;
            #pragma unroll
            for (int i = tid; i < 1024; i += 512) {
                int row = i >> 3, j = i & 7;
                cp16(sb + buf * BUF + AOFF + t * 16384 + SWZ((uint32_t)(row * 128 + j * 16)),
                     Ap + (size_t)(row0 + row) * K + c * 64 + j * 8);
            }
        }
    };
    float ar[2][8];
    auto load_A_regs = [&](int c) {
        #pragma unroll
        for (int t = 0; t < 2; ++t) {
            int g = tid + t * 512;
            int row = g >> 3, j = g & 7;
            int grow = row0 + row;
            float4 f0 = make_float4(0.f, 0.f, 0.f, 0.f), f1 = f0;
            if (grow < n) {
                const float* ap = A + (size_t)grow * K + c * 64 + j * 8;
                f0 = *(const float4*)ap;
                f1 = *(const float4*)(ap + 4);
            }
            ar[t][0] = f0.x; ar[t][1] = f0.y; ar[t][2] = f0.z; ar[t][3] = f0.w;
            ar[t][4] = f1.x; ar[t][5] = f1.y; ar[t][6] = f1.z; ar[t][7] = f1.w;
        }
    };
    auto convert_store_A = [&](int buf) {
        #pragma unroll
        for (int t = 0; t < 2; ++t) {
            int g = tid + t * 512;
            int row = g >> 3, j = g & 7;
            uint32_t hv[4], lv[4];
            #pragma unroll
            for (int q = 0; q < 4; ++q) {
                float fa = ar[t][2 * q], fb = ar[t][2 * q + 1];
                __nv_bfloat16 ha = __float2bfloat16(fa);
                __nv_bfloat16 hb = __float2bfloat16(fb);
                __nv_bfloat162 hp = __halves2bfloat162(ha, hb);
                hv[q] = *reinterpret_cast<uint32_t*>(&hp);
                __nv_bfloat162 lp = __floats2bfloat162_rn(
                    fa - __bfloat162float(ha), fb - __bfloat162float(hb));
                lv[q] = *reinterpret_cast<uint32_t*>(&lp);
            }
            uint32_t off = SWZ((uint32_t)(row * 128 + j * 16));
            *(uint4*)(smem + buf * BUF + AOFF + off)         = make_uint4(hv[0], hv[1], hv[2], hv[3]);
            *(uint4*)(smem + buf * BUF + AOFF + 16384 + off) = make_uint4(lv[0], lv[1], lv[2], lv[3]);
        }
    };

    const uint32_t b_tile_hi = BOFF + ((warp_n >> 1) * 2) * 16384;
    const int b_row_base = (warp_n & 1) * 64 + ((lane >> 4) << 3) + (lane & 7);
    const uint32_t b_colb = ((lane >> 3) & 1) * 16;

    stage_B(0, 0);
    if (ASPLIT) {
        stage_A_async(0, 0);
        CP_COMMIT();
    } else {
        CP_COMMIT();
        load_A_regs(0);
        convert_store_A(0);
    }
    CP_WAIT0();
    __syncthreads();

    for (int c = 0; c < NC; ++c) {
        const int buf = c & 1, nb = buf ^ 1;
        const bool has_next = (c + 1 < NC);
        if (has_next) {
            stage_B(c + 1, nb);
            if (ASPLIT) stage_A_async(c + 1, nb);
            CP_COMMIT();
            if (!ASPLIT) load_A_regs(c + 1);
        }

        const uint32_t abase = sb + buf * BUF + AOFF;
        const uint32_t bbase_h = sb + buf * BUF + b_tile_hi;
        #pragma unroll
        for (int ks = 0; ks < 4; ++ks) {
            uint32_t ahf[2][4], alf[2][4];
            #pragma unroll
            for (int m = 0; m < 2; ++m) {
                uint32_t off = SWZ((uint32_t)((warp_m * 32 + m * 16 + (lane & 15)) * 128
                                              + (((lane >> 4) << 3) + ks * 16) * 2));
                ldsm_x4(abase + off,         ahf[m][0], ahf[m][1], ahf[m][2], ahf[m][3]);
                ldsm_x4(abase + 16384 + off, alf[m][0], alf[m][1], alf[m][2], alf[m][3]);
            }
            #pragma unroll
            for (int p = 0; p < 4; ++p) {
                uint32_t off = SWZ((uint32_t)((b_row_base + p * 16) * 128
                                              + ks * 32 + b_colb));
                uint32_t bh0, bh1, bh2, bh3, bl0, bl1, bl2, bl3;
                ldsm_x4(bbase_h + off,         bh0, bh1, bh2, bh3);
                ldsm_x4(bbase_h + 16384 + off, bl0, bl1, bl2, bl3);
                #pragma unroll
                for (int m = 0; m < 2; ++m) {
                    mma_bf16(acc[m][p * 2 + 0], ahf[m], bh0, bh1);
                    mma_bf16(acc[m][p * 2 + 0], ahf[m], bl0, bl1);
                    mma_bf16(acc[m][p * 2 + 0], alf[m], bh0, bh1);
                    mma_bf16(acc[m][p * 2 + 1], ahf[m], bh2, bh3);
                    mma_bf16(acc[m][p * 2 + 1], ahf[m], bl2, bl3);
                    mma_bf16(acc[m][p * 2 + 1], alf[m], bh2, bh3);
                }
            }
        }

        if (has_next) {
            if (!ASPLIT) convert_store_A(nb);
            CP_WAIT0();
        }
        __syncthreads();
    }

    const bool is_z = warp_n >= 2;
    const int coln0 = (warp_n & 1) * 64;
    #pragma unroll
    for (int m = 0; m < 2; ++m) {
        int r0 = row0 + warp_m * 32 + m * 16 + (lane >> 2);
        int r1 = r0 + 8;
        #pragma unroll
        for (int f = 0; f < 8; ++f) {
            int col = coln0 + f * 8 + (lane & 3) * 2;
            if (is_z) {
                if (r0 < n)
                    *(__half2*)(Cz + (size_t)r0 * 128 + col) =
                        __floats2half2_rn(acc[m][f][0], acc[m][f][1]);
                if (r1 < n)
                    *(__half2*)(Cz + (size_t)r1 * 128 + col) =
                        __floats2half2_rn(acc[m][f][2], acc[m][f][3]);
            } else {
                if (r0 < n)
                    *(float2*)(Cs + (size_t)r0 * 128 + col) =
                        make_float2(acc[m][f][0], acc[m][f][1]);
                if (r1 < n)
                    *(float2*)(Cs + (size_t)r1 * 128 + col) =
                        make_float2(acc[m][f][2], acc[m][f][3]);
            }
        }
    }
}

// ---------------------------------------------------------------------------
// Warp-level gather core: acc = sum_{j in N(w)} z[j, 4*lane .. 4*lane+3]
// Unrolled x4 for L2-latency hiding.
// ---------------------------------------------------------------------------
__device__ __forceinline__ void gather_row(const uint2* __restrict__ zp,
                                           int st, int en, int lane,
                                           float& a0, float& a1,
                                           float& a2, float& a3) {
    int k = st;
    for (; k + 3 < en; k += 4) {
        int j0 = __ldg(&g_csr[k]);
        int j1 = __ldg(&g_csr[k + 1]);
        int j2 = __ldg(&g_csr[k + 2]);
        int j3 = __ldg(&g_csr[k + 3]);
        uint2 u0 = __ldg(&zp[(size_t)j0 * 32 + lane]);
        uint2 u1 = __ldg(&zp[(size_t)j1 * 32 + lane]);
        uint2 u2 = __ldg(&zp[(size_t)j2 * 32 + lane]);
        uint2 u3 = __ldg(&zp[(size_t)j3 * 32 + lane]);
        float2 f;
        f = __half22float2(*(const __half2*)&u0.x); a0 += f.x; a1 += f.y;
        f = __half22float2(*(const __half2*)&u0.y); a2 += f.x; a3 += f.y;
        f = __half22float2(*(const __half2*)&u1.x); a0 += f.x; a1 += f.y;
        f = __half22float2(*(const __half2*)&u1.y); a2 += f.x; a3 += f.y;
        f = __half22float2(*(const __half2*)&u2.x); a0 += f.x; a1 += f.y;
        f = __half22float2(*(const __half2*)&u2.y); a2 += f.x; a3 += f.y;
        f = __half22float2(*(const __half2*)&u3.x); a0 += f.x; a1 += f.y;
        f = __half22float2(*(const __half2*)&u3.y); a2 += f.x; a3 += f.y;
    }
    for (; k < en; ++k) {
        int j0 = __ldg(&g_csr[k]);
        uint2 u0 = __ldg(&zp[(size_t)j0 * 32 + lane]);
        float2 f;
        f = __half22float2(*(const __half2*)&u0.x); a0 += f.x; a1 += f.y;
        f = __half22float2(*(const __half2*)&u0.y); a2 += f.x; a3 += f.y;
    }
}

// ---------------------------------------------------------------------------
// SpMM1: h1 = relu(s + gather/deg), written as bf16 hi/lo split for GEMM2.
// ---------------------------------------------------------------------------
__global__ __launch_bounds__(256) void spmm1_kernel(
    const __half* __restrict__ z, const float* __restrict__ s,
    __nv_bfloat16* __restrict__ hhi, __nv_bfloat16* __restrict__ hlo, int n) {
    int w = (blockIdx.x * blockDim.x + threadIdx.x) >> 5;
    if (w >= n) return;
    int lane = threadIdx.x & 31;
    int st = g_rowptr[w], en = g_rowptr[w + 1];
    float a0 = 0.f, a1 = 0.f, a2 = 0.f, a3 = 0.f;
    gather_row((const uint2*)z, st, en, lane, a0, a1, a2, a3);
    float inv = 1.0f / (float)(en - st + 1);
    float4 sv = __ldg(&((const float4*)s)[(size_t)w * 32 + lane]);
    float o0 = fmaxf(sv.x + a0 * inv, 0.f);
    float o1 = fmaxf(sv.y + a1 * inv, 0.f);
    float o2 = fmaxf(sv.z + a2 * inv, 0.f);
    float o3 = fmaxf(sv.w + a3 * inv, 0.f);
    __nv_bfloat16 h0 = __float2bfloat16(o0), h1 = __float2bfloat16(o1);
    __nv_bfloat16 h2 = __float2bfloat16(o2), h3 = __float2bfloat16(o3);
    __nv_bfloat162 hp0 = __halves2bfloat162(h0, h1);
    __nv_bfloat162 hp1 = __halves2bfloat162(h2, h3);
    ((uint2*)hhi)[(size_t)w * 32 + lane] =
        make_uint2(*reinterpret_cast<uint32_t*>(&hp0),
                   *reinterpret_cast<uint32_t*>(&hp1));
    __nv_bfloat162 lp0 = __floats2bfloat162_rn(o0 - __bfloat162float(h0),
                                               o1 - __bfloat162float(h1));
    __nv_bfloat162 lp1 = __floats2bfloat162_rn(o2 - __bfloat162float(h2),
                                               o3 - __bfloat162float(h3));
    ((uint2*)hlo)[(size_t)w * 32 + lane] =
        make_uint2(*reinterpret_cast<uint32_t*>(&lp0),
                   *reinterpret_cast<uint32_t*>(&lp1));
}

// ---------------------------------------------------------------------------
// SpMM2 + MLP + log_softmax fused. Warp per node: gather -> h2 row in regs ->
// stage to smem row -> lane=class dot products -> softmax -> out.
// ---------------------------------------------------------------------------
__global__ __launch_bounds__(256) void spmm2_mlp_kernel(
    const __half* __restrict__ z, const float* __restrict__ s,
    const float* __restrict__ W, const float* __restrict__ bias,
    float* __restrict__ out, int n) {
    __shared__ float Ws[NCLASS * 129];    // bank = (c + k) % 32, conflict-free
    __shared__ float rowbuf[8][136];      // 16B-aligned rows (136*4 = 544)
    const int tid = threadIdx.x;
    for (int i = tid; i < NCLASS * 128; i += 256) {
        int c = i >> 7, k = i & 127;
        Ws[c * 129 + k] = W[i];
    }
    __syncthreads();

    const int lane = tid & 31;
    const int wid  = tid >> 5;
    int w = blockIdx.x * 8 + wid;
    if (w >= n) return;

    int st = g_rowptr[w], en = g_rowptr[w + 1];
    float a0 = 0.f, a1 = 0.f, a2 = 0.f, a3 = 0.f;
    gather_row((const uint2*)z, st, en, lane, a0, a1, a2, a3);
    float inv = 1.0f / (float)(en - st + 1);
    float4 sv = __ldg(&((const float4*)s)[(size_t)w * 32 + lane]);
    float o0 = fmaxf(sv.x + a0 * inv, 0.f);
    float o1 = fmaxf(sv.y + a1 * inv, 0.f);
    float o2 = fmaxf(sv.z + a2 * inv, 0.f);
    float o3 = fmaxf(sv.w + a3 * inv, 0.f);

    // Stage row (warp-private) and run MLP: lane = class, lanes 0-7 dual.
    *(float4*)&rowbuf[wid][lane * 4] = make_float4(o0, o1, o2, o3);
    __syncwarp();

    float v0 = __ldg(&bias[lane]);
    float v1 = (lane < NCLASS - 32) ? __ldg(&bias[lane + 32]) : 0.f;
    const float* hr = rowbuf[wid];
    #pragma unroll 8
    for (int k = 0; k < 128; ++k) {
        float hh = hr[k];                       // broadcast
        v0 = fmaf(hh, Ws[lane * 129 + k], v0);
        if (lane < 8) v1 = fmaf(hh, Ws[(lane + 32) * 129 + k], v1);
    }
    float m = v0;
    if (lane < 8) m = fmaxf(m, v1);
    #pragma unroll
    for (int off = 16; off >= 1; off >>= 1)
        m = fmaxf(m, __shfl_xor_sync(0xffffffffu, m, off));
    float sum = expf(v0 - m) + ((lane < 8) ? expf(v1 - m) : 0.f);
    #pragma unroll
    for (int off = 16; off >= 1; off >>= 1)
        sum += __shfl_xor_sync(0xffffffffu, sum, off);
    float ls = logf(sum);
    float* orow = out + (size_t)w * NCLASS;
    orow[lane] = v0 - m - ls;
    if (lane < 8) orow[32 + lane] = v1 - m - ls;
}

// ---------------------------------------------------------------------------
// Launch
// ---------------------------------------------------------------------------
extern "C" void kernel_launch(void* const* d_in, const int* in_sizes, int n_in,
                              void* d_out, int out_size) {
    const float* x    = (const float*)d_in[0];
    const float* W1   = (const float*)d_in[1];
    const float* W2   = (const float*)d_in[2];
    const float* mlpW = (const float*)d_in[3];
    const float* mlpb = (const float*)d_in[4];
    const int*   rows = (const int*)d_in[5];
    const int*   cols = (const int*)d_in[6];
    const int n = in_sizes[0] / NFEAT;
    const int e = in_sizes[5];
    float* out = (float*)d_out;

    void *p_s, *p_z, *p_h1h, *p_h1l;
    void *p_b1s_hi, *p_b1s_lo, *p_b1n_hi, *p_b1n_lo;
    void *p_b2s_hi, *p_b2s_lo, *p_b2n_hi, *p_b2n_lo;
    cudaGetSymbolAddress(&p_s, g_s);
    cudaGetSymbolAddress(&p_z, g_z);
    cudaGetSymbolAddress(&p_h1h, g_h1_hi);
    cudaGetSymbolAddress(&p_h1l, g_h1_lo);
    cudaGetSymbolAddress(&p_b1s_hi, g_b1s_hi);
    cudaGetSymbolAddress(&p_b1s_lo, g_b1s_lo);
    cudaGetSymbolAddress(&p_b1n_hi, g_b1n_hi);
    cudaGetSymbolAddress(&p_b1n_lo, g_b1n_lo);
    cudaGetSymbolAddress(&p_b2s_hi, g_b2s_hi);
    cudaGetSymbolAddress(&p_b2s_lo, g_b2s_lo);
    cudaGetSymbolAddress(&p_b2n_hi, g_b2n_hi);
    cudaGetSymbolAddress(&p_b2n_lo, g_b2n_lo);

    constexpr int SMEM = 2 * 98304;   // 192 KB double buffer
    cudaFuncSetAttribute(mma_gemm_kernel<256, false>,
                         cudaFuncAttributeMaxDynamicSharedMemorySize, SMEM);
    cudaFuncSetAttribute(mma_gemm_kernel<128, true>,
                         cudaFuncAttributeMaxDynamicSharedMemorySize, SMEM);

    // Prep (weight split + cnt zero) and CSR build
    prep_kernel<<<(n + 255) / 256, 256>>>(W1, W2, n);
    count_kernel<<<(e + 255) / 256, 256>>>(rows, e);
    scan_kernel<<<1, 1024>>>(n, e);
    fill_kernel<<<(e + 255) / 256, 256>>>(rows, cols, e);

    const int gx = (n + 127) / 128;
    const int spmm_blocks = (n * 32 + 255) / 256;

    // Layer 1: s = x@W1top^T (fp32), z = x@W1bot^T (fp16), one pass over x
    mma_gemm_kernel<256, false><<<gx, 512, SMEM>>>(
        x, nullptr, nullptr,
        (const __nv_bfloat16*)p_b1s_hi, (const __nv_bfloat16*)p_b1s_lo,
        (const __nv_bfloat16*)p_b1n_hi, (const __nv_bfloat16*)p_b1n_lo,
        (float*)p_s, (__half*)p_z, n);
    spmm1_kernel<<<spmm_blocks, 256>>>(
        (const __half*)p_z, (const float*)p_s,
        (__nv_bfloat16*)p_h1h, (__nv_bfloat16*)p_h1l, n);

    // Layer 2: A pre-split bf16 (pure cp.async path)
    mma_gemm_kernel<128, true><<<gx, 512, SMEM>>>(
        nullptr, (const __nv_bfloat16*)p_h1h, (const __nv_bfloat16*)p_h1l,
        (const __nv_bfloat16*)p_b2s_hi, (const __nv_bfloat16*)p_b2s_lo,
        (const __nv_bfloat16*)p_b2n_hi, (const __nv_bfloat16*)p_b2n_lo,
        (float*)p_s, (__half*)p_z, n);

    // SpMM2 + MLP + log_softmax fused
    spmm2_mlp_kernel<<<(n + 7) / 8, 256>>>(
        (const __half*)p_z, (const float*)p_s, mlpW, mlpb, out, n);
}

// round 9
// speedup vs baseline: 2.4365x; 1.1890x over previous
#include <cuda_runtime.h>
#include <cuda_bf16.h>
#include <cuda_fp16.h>
#include <math.h>
#include <stdint.h>

// Problem constants
#define NFEAT   256
#define NHID    128
#define NCLASS  40
#define MAXN    100000
#define MAXE    3200000
#define ELLW    96            // ELL width: P(Poisson(32) > 96) ~ 1e-20
#define NPAD    (MAXN + 128)  // rows padded so cp.async tail reads stay in-bounds

// ---------------------------------------------------------------------------
// Static device scratch
// ---------------------------------------------------------------------------
__device__ int   g_cnt[MAXN];                      // degree (atomic slot counter)
__device__ int   g_ell[(size_t)MAXN * ELLW];       // ELL adjacency (38.4 MB)
__device__ float  g_s[(size_t)MAXN * NHID];        // self-projection (fp32)
__device__ __half g_z[(size_t)MAXN * NHID];        // neigh-projection (fp16)
__device__ __nv_bfloat16 g_h1_hi[(size_t)NPAD * NHID];  // h1 pre-split for GEMM2
__device__ __nv_bfloat16 g_h1_lo[(size_t)NPAD * NHID];
// bf16-split weights, [128 out-rows, K in-cols] K-major
__device__ __nv_bfloat16 g_b1s_hi[128 * 256], g_b1s_lo[128 * 256];
__device__ __nv_bfloat16 g_b1n_hi[128 * 256], g_b1n_lo[128 * 256];
__device__ __nv_bfloat16 g_b2s_hi[128 * 128], g_b2s_lo[128 * 128];
__device__ __nv_bfloat16 g_b2n_hi[128 * 128], g_b2n_lo[128 * 128];

// ---------------------------------------------------------------------------
// Helpers
// ---------------------------------------------------------------------------
__device__ __forceinline__ uint32_t smem_u32(const void* p) {
    uint32_t a;
    asm("{ .reg .u64 t; cvta.to.shared.u64 t, %1; cvt.u32.u64 %0, t; }"
        : "=r"(a) : "l"(p));
    return a;
}

#define SWZ(x) ((x) ^ (((x) >> 3) & 0x70))

__device__ __forceinline__ void ldsm_x4(uint32_t addr, uint32_t& r0, uint32_t& r1,
                                        uint32_t& r2, uint32_t& r3) {
    asm volatile("ldmatrix.sync.aligned.m8n8.x4.shared.b16 {%0,%1,%2,%3}, [%4];"
                 : "=r"(r0), "=r"(r1), "=r"(r2), "=r"(r3) : "r"(addr));
}

__device__ __forceinline__ void mma_bf16(float* d, const uint32_t* a,
                                         uint32_t b0, uint32_t b1) {
    asm volatile(
        "mma.sync.aligned.m16n8k16.row.col.f32.bf16.bf16.f32 "
        "{%0,%1,%2,%3}, {%4,%5,%6,%7}, {%8,%9}, {%0,%1,%2,%3};"
        : "+f"(d[0]), "+f"(d[1]), "+f"(d[2]), "+f"(d[3])
        : "r"(a[0]), "r"(a[1]), "r"(a[2]), "r"(a[3]), "r"(b0), "r"(b1));
}

__device__ __forceinline__ void cp16(uint32_t dst, const void* src) {
    asm volatile("cp.async.cg.shared.global [%0], [%1], 16;"
                 :: "r"(dst), "l"(src));
}
#define CP_COMMIT() asm volatile("cp.async.commit_group;" ::: "memory")
#define CP_WAIT0()  asm volatile("cp.async.wait_group 0;" ::: "memory")

// ---------------------------------------------------------------------------
// Merged prep: W1 split (idx<32768), W2 split (idx<16384), zero g_cnt (idx<n)
// ---------------------------------------------------------------------------
__global__ void prep_kernel(const float* __restrict__ W1,
                            const float* __restrict__ W2, int n) {
    int idx = blockIdx.x * blockDim.x + threadIdx.x;
    if (idx < 128 * 256) {
        int j = idx >> 8, k = idx & 255;
        float a = W1[j * 512 + k];
        __nv_bfloat16 ha = __float2bfloat16(a);
        g_b1s_hi[idx] = ha;
        g_b1s_lo[idx] = __float2bfloat16(a - __bfloat162float(ha));
        float b = W1[j * 512 + 256 + k];
        __nv_bfloat16 hb = __float2bfloat16(b);
        g_b1n_hi[idx] = hb;
        g_b1n_lo[idx] = __float2bfloat16(b - __bfloat162float(hb));
    }
    if (idx < 128 * 128) {
        int j = idx >> 7, k = idx & 127;
        float a = W2[j * 256 + k];
        __nv_bfloat16 ha = __float2bfloat16(a);
        g_b2s_hi[idx] = ha;
        g_b2s_lo[idx] = __float2bfloat16(a - __bfloat162float(ha));
        float b = W2[j * 256 + 128 + k];
        __nv_bfloat16 hb = __float2bfloat16(b);
        g_b2n_hi[idx] = hb;
        g_b2n_lo[idx] = __float2bfloat16(b - __bfloat162float(hb));
    }
    if (idx < n) g_cnt[idx] = 0;
}

// ---------------------------------------------------------------------------
// Merged double-buffered GEMM (bf16 split-3, mma.sync):
//   s[blk,128] = A @ Bs^T (fp32 out),  z[blk,128] = A @ Bn^T (fp16 out)
// Block 128 rows x 256 out-cols, 512 threads = 16 warps (4 M x 4 N of 32x64).
// EFILL: blocks with blockIdx.x >= gemm_blocks instead build the ELL
// adjacency (atomic slot alloc) — they schedule into the GEMM tail wave.
// ---------------------------------------------------------------------------
template <int K, bool ASPLIT, bool EFILL>
__global__ __launch_bounds__(512, 1) void mma_gemm_kernel(
    const float* __restrict__ A,
    const __nv_bfloat16* __restrict__ Ah, const __nv_bfloat16* __restrict__ Al,
    const __nv_bfloat16* __restrict__ Bsh, const __nv_bfloat16* __restrict__ Bsl,
    const __nv_bfloat16* __restrict__ Bnh, const __nv_bfloat16* __restrict__ Bnl,
    float* __restrict__ Cs, __half* __restrict__ Cz, int n,
    int gemm_blocks, const int* __restrict__ rows,
    const int* __restrict__ cols, int e) {
    // ---- ELL-fill role (tail blocks) ----
    if (EFILL && (int)blockIdx.x >= gemm_blocks) {
        const int fb  = blockIdx.x - gemm_blocks;
        const int nfb = gridDim.x - gemm_blocks;
        const int tid = threadIdx.x;
        const int total4 = e >> 2;
        const int4* r4p = (const int4*)rows;
        const int4* c4p = (const int4*)cols;
        for (int i = fb * 512 + tid; i < total4; i += nfb * 512) {
            int4 r = __ldg(&r4p[i]);
            int4 c = __ldg(&c4p[i]);
            int p;
            p = atomicAdd(&g_cnt[r.x], 1); if (p < ELLW) g_ell[(size_t)r.x * ELLW + p] = c.x;
            p = atomicAdd(&g_cnt[r.y], 1); if (p < ELLW) g_ell[(size_t)r.y * ELLW + p] = c.y;
            p = atomicAdd(&g_cnt[r.z], 1); if (p < ELLW) g_ell[(size_t)r.z * ELLW + p] = c.z;
            p = atomicAdd(&g_cnt[r.w], 1); if (p < ELLW) g_ell[(size_t)r.w * ELLW + p] = c.w;
        }
        if (fb == 0) {       // scalar tail (e % 4)
            for (int i = (total4 << 2) + tid; i < e; i += 512) {
                int r = __ldg(&rows[i]), c = __ldg(&cols[i]);
                int p = atomicAdd(&g_cnt[r], 1);
                if (p < ELLW) g_ell[(size_t)r * ELLW + p] = c;
            }
        }
        return;
    }

    extern __shared__ char smem[];
    constexpr int BUF  = 98304;
    constexpr int AOFF = 0;
    constexpr int BOFF = 32768;
    constexpr int NC   = K / 64;
    const uint32_t sb = smem_u32(smem);
    const int tid    = threadIdx.x;
    const int lane   = tid & 31;
    const int wid    = tid >> 5;
    const int warp_m = wid & 3;
    const int warp_n = wid >> 2;
    const int row0   = blockIdx.x * 128;

    float acc[2][8][4];
    #pragma unroll
    for (int m = 0; m < 2; ++m)
        #pragma unroll
        for (int f = 0; f < 8; ++f)
            #pragma unroll
            for (int q = 0; q < 4; ++q) acc[m][f][q] = 0.f;

    auto stage_B = [&](int c, int buf) {
        #pragma unroll
        for (int t = 0; t < 4; ++t) {
            const __nv_bfloat16* B = (t == 0) ? Bsh : (t == 1) ? Bsl
                                   : (t == 2) ? Bnh : Bnl;
            #pragma unroll
            for (int i = tid; i < 1024; i += 512) {
                int row = i >> 3, j = i & 7;
                cp16(sb + buf * BUF + BOFF + t * 16384 + SWZ((uint32_t)(row * 128 + j * 16)),
                     B + (size_t)row * K + c * 64 + j * 8);
            }
        }
    };
    auto stage_A_async = [&](int c, int buf) {
        #pragma unroll
        for (int t = 0; t < 2; ++t) {
            const __nv_bfloat16* Ap = t ? Al : Ah;
            #pragma unroll
            for (int i = tid; i < 1024; i += 512) {
                int row = i >> 3, j = i & 7;
                cp16(sb + buf * BUF + AOFF + t * 16384 + SWZ((uint32_t)(row * 128 + j * 16)),
                     Ap + (size_t)(row0 + row) * K + c * 64 + j * 8);
            }
        }
    };
    float ar[2][8];
    auto load_A_regs = [&](int c) {
        #pragma unroll
        for (int t = 0; t < 2; ++t) {
            int g = tid + t * 512;
            int row = g >> 3, j = g & 7;
            int grow = row0 + row;
            float4 f0 = make_float4(0.f, 0.f, 0.f, 0.f), f1 = f0;
            if (grow < n) {
                const float* ap = A + (size_t)grow * K + c * 64 + j * 8;
                f0 = *(const float4*)ap;
                f1 = *(const float4*)(ap + 4);
            }
            ar[t][0] = f0.x; ar[t][1] = f0.y; ar[t][2] = f0.z; ar[t][3] = f0.w;
            ar[t][4] = f1.x; ar[t][5] = f1.y; ar[t][6] = f1.z; ar[t][7] = f1.w;
        }
    };
    auto convert_store_A = [&](int buf) {
        #pragma unroll
        for (int t = 0; t < 2; ++t) {
            int g = tid + t * 512;
            int row = g >> 3, j = g & 7;
            uint32_t hv[4], lv[4];
            #pragma unroll
            for (int q = 0; q < 4; ++q) {
                float fa = ar[t][2 * q], fb = ar[t][2 * q + 1];
                __nv_bfloat16 ha = __float2bfloat16(fa);
                __nv_bfloat16 hb = __float2bfloat16(fb);
                __nv_bfloat162 hp = __halves2bfloat162(ha, hb);
                hv[q] = *reinterpret_cast<uint32_t*>(&hp);
                __nv_bfloat162 lp = __floats2bfloat162_rn(
                    fa - __bfloat162float(ha), fb - __bfloat162float(hb));
                lv[q] = *reinterpret_cast<uint32_t*>(&lp);
            }
            uint32_t off = SWZ((uint32_t)(row * 128 + j * 16));
            *(uint4*)(smem + buf * BUF + AOFF + off)         = make_uint4(hv[0], hv[1], hv[2], hv[3]);
            *(uint4*)(smem + buf * BUF + AOFF + 16384 + off) = make_uint4(lv[0], lv[1], lv[2], lv[3]);
        }
    };

    const uint32_t b_tile_hi = BOFF + ((warp_n >> 1) * 2) * 16384;
    const int b_row_base = (warp_n & 1) * 64 + ((lane >> 4) << 3) + (lane & 7);
    const uint32_t b_colb = ((lane >> 3) & 1) * 16;

    stage_B(0, 0);
    if (ASPLIT) {
        stage_A_async(0, 0);
        CP_COMMIT();
    } else {
        CP_COMMIT();
        load_A_regs(0);
        convert_store_A(0);
    }
    CP_WAIT0();
    __syncthreads();

    for (int c = 0; c < NC; ++c) {
        const int buf = c & 1, nb = buf ^ 1;
        const bool has_next = (c + 1 < NC);
        if (has_next) {
            stage_B(c + 1, nb);
            if (ASPLIT) stage_A_async(c + 1, nb);
            CP_COMMIT();
            if (!ASPLIT) load_A_regs(c + 1);
        }

        const uint32_t abase = sb + buf * BUF + AOFF;
        const uint32_t bbase_h = sb + buf * BUF + b_tile_hi;
        #pragma unroll
        for (int ks = 0; ks < 4; ++ks) {
            uint32_t ahf[2][4], alf[2][4];
            #pragma unroll
            for (int m = 0; m < 2; ++m) {
                uint32_t off = SWZ((uint32_t)((warp_m * 32 + m * 16 + (lane & 15)) * 128
                                              + (((lane >> 4) << 3) + ks * 16) * 2));
                ldsm_x4(abase + off,         ahf[m][0], ahf[m][1], ahf[m][2], ahf[m][3]);
                ldsm_x4(abase + 16384 + off, alf[m][0], alf[m][1], alf[m][2], alf[m][3]);
            }
            #pragma unroll
            for (int p = 0; p < 4; ++p) {
                uint32_t off = SWZ((uint32_t)((b_row_base + p * 16) * 128
                                              + ks * 32 + b_colb));
                uint32_t bh0, bh1, bh2, bh3, bl0, bl1, bl2, bl3;
                ldsm_x4(bbase_h + off,         bh0, bh1, bh2, bh3);
                ldsm_x4(bbase_h + 16384 + off, bl0, bl1, bl2, bl3);
                #pragma unroll
                for (int m = 0; m < 2; ++m) {
                    mma_bf16(acc[m][p * 2 + 0], ahf[m], bh0, bh1);
                    mma_bf16(acc[m][p * 2 + 0], ahf[m], bl0, bl1);
                    mma_bf16(acc[m][p * 2 + 0], alf[m], bh0, bh1);
                    mma_bf16(acc[m][p * 2 + 1], ahf[m], bh2, bh3);
                    mma_bf16(acc[m][p * 2 + 1], ahf[m], bl2, bl3);
                    mma_bf16(acc[m][p * 2 + 1], alf[m], bh2, bh3);
                }
            }
        }

        if (has_next) {
            if (!ASPLIT) convert_store_A(nb);
            CP_WAIT0();
        }
        __syncthreads();
    }

    const bool is_z = warp_n >= 2;
    const int coln0 = (warp_n & 1) * 64;
    #pragma unroll
    for (int m = 0; m < 2; ++m) {
        int r0 = row0 + warp_m * 32 + m * 16 + (lane >> 2);
        int r1 = r0 + 8;
        #pragma unroll
        for (int f = 0; f < 8; ++f) {
            int col = coln0 + f * 8 + (lane & 3) * 2;
            if (is_z) {
                if (r0 < n)
                    *(__half2*)(Cz + (size_t)r0 * 128 + col) =
                        __floats2half2_rn(acc[m][f][0], acc[m][f][1]);
                if (r1 < n)
                    *(__half2*)(Cz + (size_t)r1 * 128 + col) =
                        __floats2half2_rn(acc[m][f][2], acc[m][f][3]);
            } else {
                if (r0 < n)
                    *(float2*)(Cs + (size_t)r0 * 128 + col) =
                        make_float2(acc[m][f][0], acc[m][f][1]);
                if (r1 < n)
                    *(float2*)(Cs + (size_t)r1 * 128 + col) =
                        make_float2(acc[m][f][2], acc[m][f][3]);
            }
        }
    }
}

// ---------------------------------------------------------------------------
// Warp-level gather over ELL row: int4 index loads (4 edges per load).
// ---------------------------------------------------------------------------
__device__ __forceinline__ void gather_row(const uint2* __restrict__ zp,
                                           const int* __restrict__ ell, int len,
                                           int lane,
                                           float& a0, float& a1,
                                           float& a2, float& a3) {
    int k = 0;
    for (; k + 3 < len; k += 4) {
        int4 j4 = __ldg((const int4*)(ell + k));       // 16B-aligned (k%4==0)
        uint2 u0 = __ldg(&zp[(size_t)j4.x * 32 + lane]);
        uint2 u1 = __ldg(&zp[(size_t)j4.y * 32 + lane]);
        uint2 u2 = __ldg(&zp[(size_t)j4.z * 32 + lane]);
        uint2 u3 = __ldg(&zp[(size_t)j4.w * 32 + lane]);
        float2 f;
        f = __half22float2(*(const __half2*)&u0.x); a0 += f.x; a1 += f.y;
        f = __half22float2(*(const __half2*)&u0.y); a2 += f.x; a3 += f.y;
        f = __half22float2(*(const __half2*)&u1.x); a0 += f.x; a1 += f.y;
        f = __half22float2(*(const __half2*)&u1.y); a2 += f.x; a3 += f.y;
        f = __half22float2(*(const __half2*)&u2.x); a0 += f.x; a1 += f.y;
        f = __half22float2(*(const __half2*)&u2.y); a2 += f.x; a3 += f.y;
        f = __half22float2(*(const __half2*)&u3.x); a0 += f.x; a1 += f.y;
        f = __half22float2(*(const __half2*)&u3.y); a2 += f.x; a3 += f.y;
    }
    for (; k < len; ++k) {
        int j0 = __ldg(&ell[k]);
        uint2 u0 = __ldg(&zp[(size_t)j0 * 32 + lane]);
        float2 f;
        f = __half22float2(*(const __half2*)&u0.x); a0 += f.x; a1 += f.y;
        f = __half22float2(*(const __half2*)&u0.y); a2 += f.x; a3 += f.y;
    }
}

// ---------------------------------------------------------------------------
// SpMM1: h1 = relu(s + gather/(deg+1)), written as bf16 hi/lo split for GEMM2.
// ---------------------------------------------------------------------------
__global__ __launch_bounds__(256) void spmm1_kernel(
    const __half* __restrict__ z, const float* __restrict__ s,
    __nv_bfloat16* __restrict__ hhi, __nv_bfloat16* __restrict__ hlo, int n) {
    int w = (blockIdx.x * blockDim.x + threadIdx.x) >> 5;
    if (w >= n) return;
    int lane = threadIdx.x & 31;
    int deg = __ldg(&g_cnt[w]);
    int len = min(deg, ELLW);
    float a0 = 0.f, a1 = 0.f, a2 = 0.f, a3 = 0.f;
    gather_row((const uint2*)z, g_ell + (size_t)w * ELLW, len, lane, a0, a1, a2, a3);
    float inv = 1.0f / (float)(deg + 1);
    float4 sv = __ldg(&((const float4*)s)[(size_t)w * 32 + lane]);
    float o0 = fmaxf(sv.x + a0 * inv, 0.f);
    float o1 = fmaxf(sv.y + a1 * inv, 0.f);
    float o2 = fmaxf(sv.z + a2 * inv, 0.f);
    float o3 = fmaxf(sv.w + a3 * inv, 0.f);
    __nv_bfloat16 h0 = __float2bfloat16(o0), h1 = __float2bfloat16(o1);
    __nv_bfloat16 h2 = __float2bfloat16(o2), h3 = __float2bfloat16(o3);
    __nv_bfloat162 hp0 = __halves2bfloat162(h0, h1);
    __nv_bfloat162 hp1 = __halves2bfloat162(h2, h3);
    ((uint2*)hhi)[(size_t)w * 32 + lane] =
        make_uint2(*reinterpret_cast<uint32_t*>(&hp0),
                   *reinterpret_cast<uint32_t*>(&hp1));
    __nv_bfloat162 lp0 = __floats2bfloat162_rn(o0 - __bfloat162float(h0),
                                               o1 - __bfloat162float(h1));
    __nv_bfloat162 lp1 = __floats2bfloat162_rn(o2 - __bfloat162float(h2),
                                               o3 - __bfloat162float(h3));
    ((uint2*)hlo)[(size_t)w * 32 + lane] =
        make_uint2(*reinterpret_cast<uint32_t*>(&lp0),
                   *reinterpret_cast<uint32_t*>(&lp1));
}

// ---------------------------------------------------------------------------
// SpMM2 + MLP + log_softmax fused. Warp per node.
// ---------------------------------------------------------------------------
__global__ __launch_bounds__(256) void spmm2_mlp_kernel(
    const __half* __restrict__ z, const float* __restrict__ s,
    const float* __restrict__ W, const float* __restrict__ bias,
    float* __restrict__ out, int n) {
    __shared__ float Ws[NCLASS * 129];    // bank = (c + k) % 32, conflict-free
    __shared__ float rowbuf[8][136];
    const int tid = threadIdx.x;
    for (int i = tid; i < NCLASS * 128; i += 256) {
        int c = i >> 7, k = i & 127;
        Ws[c * 129 + k] = W[i];
    }
    __syncthreads();

    const int lane = tid & 31;
    const int wid  = tid >> 5;
    int w = blockIdx.x * 8 + wid;
    if (w >= n) return;

    int deg = __ldg(&g_cnt[w]);
    int len = min(deg, ELLW);
    float a0 = 0.f, a1 = 0.f, a2 = 0.f, a3 = 0.f;
    gather_row((const uint2*)z, g_ell + (size_t)w * ELLW, len, lane, a0, a1, a2, a3);
    float inv = 1.0f / (float)(deg + 1);
    float4 sv = __ldg(&((const float4*)s)[(size_t)w * 32 + lane]);
    float o0 = fmaxf(sv.x + a0 * inv, 0.f);
    float o1 = fmaxf(sv.y + a1 * inv, 0.f);
    float o2 = fmaxf(sv.z + a2 * inv, 0.f);
    float o3 = fmaxf(sv.w + a3 * inv, 0.f);

    *(float4*)&rowbuf[wid][lane * 4] = make_float4(o0, o1, o2, o3);
    __syncwarp();

    float v0 = __ldg(&bias[lane]);
    float v1 = (lane < NCLASS - 32) ? __ldg(&bias[lane + 32]) : 0.f;
    const float* hr = rowbuf[wid];
    #pragma unroll 8
    for (int k = 0; k < 128; ++k) {
        float hh = hr[k];
        v0 = fmaf(hh, Ws[lane * 129 + k], v0);
        if (lane < 8) v1 = fmaf(hh, Ws[(lane + 32) * 129 + k], v1);
    }
    float m = v0;
    if (lane < 8) m = fmaxf(m, v1);
    #pragma unroll
    for (int off = 16; off >= 1; off >>= 1)
        m = fmaxf(m, __shfl_xor_sync(0xffffffffu, m, off));
    float sum = expf(v0 - m) + ((lane < 8) ? expf(v1 - m) : 0.f);
    #pragma unroll
    for (int off = 16; off >= 1; off >>= 1)
        sum += __shfl_xor_sync(0xffffffffu, sum, off);
    float ls = logf(sum);
    float* orow = out + (size_t)w * NCLASS;
    orow[lane] = v0 - m - ls;
    if (lane < 8) orow[32 + lane] = v1 - m - ls;
}

// ---------------------------------------------------------------------------
// Launch
// ---------------------------------------------------------------------------
extern "C" void kernel_launch(void* const* d_in, const int* in_sizes, int n_in,
                              void* d_out, int out_size) {
    const float* x    = (const float*)d_in[0];
    const float* W1   = (const float*)d_in[1];
    const float* W2   = (const float*)d_in[2];
    const float* mlpW = (const float*)d_in[3];
    const float* mlpb = (const float*)d_in[4];
    const int*   rows = (const int*)d_in[5];
    const int*   cols = (const int*)d_in[6];
    const int n = in_sizes[0] / NFEAT;
    const int e = in_sizes[5];
    float* out = (float*)d_out;

    void *p_s, *p_z, *p_h1h, *p_h1l;
    void *p_b1s_hi, *p_b1s_lo, *p_b1n_hi, *p_b1n_lo;
    void *p_b2s_hi, *p_b2s_lo, *p_b2n_hi, *p_b2n_lo;
    cudaGetSymbolAddress(&p_s, g_s);
    cudaGetSymbolAddress(&p_z, g_z);
    cudaGetSymbolAddress(&p_h1h, g_h1_hi);
    cudaGetSymbolAddress(&p_h1l, g_h1_lo);
    cudaGetSymbolAddress(&p_b1s_hi, g_b1s_hi);
    cudaGetSymbolAddress(&p_b1s_lo, g_b1s_lo);
    cudaGetSymbolAddress(&p_b1n_hi, g_b1n_hi);
    cudaGetSymbolAddress(&p_b1n_lo, g_b1n_lo);
    cudaGetSymbolAddress(&p_b2s_hi, g_b2s_hi);
    cudaGetSymbolAddress(&p_b2s_lo, g_b2s_lo);
    cudaGetSymbolAddress(&p_b2n_hi, g_b2n_hi);
    cudaGetSymbolAddress(&p_b2n_lo, g_b2n_lo);

    constexpr int SMEM = 2 * 98304;   // 192 KB double buffer
    cudaFuncSetAttribute((const void*)mma_gemm_kernel<256, false, true>,
                         cudaFuncAttributeMaxDynamicSharedMemorySize, SMEM);
    cudaFuncSetAttribute((const void*)mma_gemm_kernel<128, true, false>,
                         cudaFuncAttributeMaxDynamicSharedMemorySize, SMEM);

    int nsm = 148;
    cudaDeviceGetAttribute(&nsm, cudaDevAttrMultiProcessorCount, 0);

    // Prep: weight split + degree-counter zero (ELL needs no count/scan)
    prep_kernel<<<(n + 255) / 256, 256>>>(W1, W2, n);

    const int gx = (n + 127) / 128;
    int fillb = nsm - (gx % nsm);          // fill the GEMM1 tail wave
    if (fillb <= 0) fillb = nsm;
    const int spmm_blocks = (n * 32 + 255) / 256;

    // Layer 1 GEMM + ELL build in tail blocks
    mma_gemm_kernel<256, false, true><<<gx + fillb, 512, SMEM>>>(
        x, nullptr, nullptr,
        (const __nv_bfloat16*)p_b1s_hi, (const __nv_bfloat16*)p_b1s_lo,
        (const __nv_bfloat16*)p_b1n_hi, (const __nv_bfloat16*)p_b1n_lo,
        (float*)p_s, (__half*)p_z, n, gx, rows, cols, e);
    spmm1_kernel<<<spmm_blocks, 256>>>(
        (const __half*)p_z, (const float*)p_s,
        (__nv_bfloat16*)p_h1h, (__nv_bfloat16*)p_h1l, n);

    // Layer 2: A pre-split bf16 (pure cp.async path)
    mma_gemm_kernel<128, true, false><<<gx, 512, SMEM>>>(
        nullptr, (const __nv_bfloat16*)p_h1h, (const __nv_bfloat16*)p_h1l,
        (const __nv_bfloat16*)p_b2s_hi, (const __nv_bfloat16*)p_b2s_lo,
        (const __nv_bfloat16*)p_b2n_hi, (const __nv_bfloat16*)p_b2n_lo,
        (float*)p_s, (__half*)p_z, n, gx, nullptr, nullptr, 0);

    // SpMM2 + MLP + log_softmax fused
    spmm2_mlp_kernel<<<(n + 7) / 8, 256>>>(
        (const __half*)p_z, (const float*)p_s, mlpW, mlpb, out, n);
}

// round 10
// speedup vs baseline: 3.0152x; 1.2375x over previous
#include <cuda_runtime.h>
#include <cuda_bf16.h>
#include <cuda_fp16.h>
#include <math.h>
#include <stdint.h>

// Problem constants
#define NFEAT   256
#define NHID    128
#define NCLASS  40
#define MAXN    100000
#define MAXE    3200000
#define ELLW    96            // ELL width: P(Poisson(32) > 96) ~ 1e-20
#define NPAD    (MAXN + 128)  // rows padded so cp.async tail reads stay in-bounds

// ---------------------------------------------------------------------------
// Static device scratch
// ---------------------------------------------------------------------------
__device__ int   g_cnt[MAXN];                      // degree (atomic slot counter)
__device__ int   g_ell[(size_t)MAXN * ELLW];       // ELL adjacency (38.4 MB)
__device__ float  g_s[(size_t)MAXN * NHID];        // self-projection (fp32)
__device__ __half g_z[(size_t)MAXN * NHID];        // neigh-projection (fp16)
__device__ __half g_h1[(size_t)NPAD * NHID];       // h1 (fp16, GEMM2 A operand)
// fp16 weights, [128 out-rows, K in-cols] K-major (= torch native slices)
__device__ __half g_w1s[128 * 256], g_w1n[128 * 256];
__device__ __half g_w2s[128 * 128], g_w2n[128 * 128];

// ---------------------------------------------------------------------------
// Helpers
// ---------------------------------------------------------------------------
__device__ __forceinline__ uint32_t smem_u32(const void* p) {
    uint32_t a;
    asm("{ .reg .u64 t; cvta.to.shared.u64 t, %1; cvt.u32.u64 %0, t; }"
        : "=r"(a) : "l"(p));
    return a;
}

#define SWZ(x) ((x) ^ (((x) >> 3) & 0x70))

__device__ __forceinline__ void ldsm_x4(uint32_t addr, uint32_t& r0, uint32_t& r1,
                                        uint32_t& r2, uint32_t& r3) {
    asm volatile("ldmatrix.sync.aligned.m8n8.x4.shared.b16 {%0,%1,%2,%3}, [%4];"
                 : "=r"(r0), "=r"(r1), "=r"(r2), "=r"(r3) : "r"(addr));
}

__device__ __forceinline__ void mma_fp16(float* d, const uint32_t* a,
                                         uint32_t b0, uint32_t b1) {
    asm volatile(
        "mma.sync.aligned.m16n8k16.row.col.f32.f16.f16.f32 "
        "{%0,%1,%2,%3}, {%4,%5,%6,%7}, {%8,%9}, {%0,%1,%2,%3};"
        : "+f"(d[0]), "+f"(d[1]), "+f"(d[2]), "+f"(d[3])
        : "r"(a[0]), "r"(a[1]), "r"(a[2]), "r"(a[3]), "r"(b0), "r"(b1));
}

__device__ __forceinline__ void cp16(uint32_t dst, const void* src) {
    asm volatile("cp.async.cg.shared.global [%0], [%1], 16;"
                 :: "r"(dst), "l"(src));
}
#define CP_COMMIT() asm volatile("cp.async.commit_group;" ::: "memory")
#define CP_WAIT0()  asm volatile("cp.async.wait_group 0;" ::: "memory")

// ---------------------------------------------------------------------------
// Merged prep: W1 -> fp16 slices (idx<32768), W2 (idx<16384), zero g_cnt
// ---------------------------------------------------------------------------
__global__ void prep_kernel(const float* __restrict__ W1,
                            const float* __restrict__ W2, int n) {
    int idx = blockIdx.x * blockDim.x + threadIdx.x;
    if (idx < 128 * 256) {
        int j = idx >> 8, k = idx & 255;
        g_w1s[idx] = __float2half_rn(W1[j * 512 + k]);
        g_w1n[idx] = __float2half_rn(W1[j * 512 + 256 + k]);
    }
    if (idx < 128 * 128) {
        int j = idx >> 7, k = idx & 127;
        g_w2s[idx] = __float2half_rn(W2[j * 256 + k]);
        g_w2n[idx] = __float2half_rn(W2[j * 256 + 128 + k]);
    }
    if (idx < n) g_cnt[idx] = 0;
}

// ---------------------------------------------------------------------------
// Merged double-buffered fp16 GEMM (mma.sync m16n8k16):
//   s[blk,128] = A @ Bs^T (fp32 out),  z[blk,128] = A @ Bn^T (fp16 out)
// Block 128 rows x 256 out-cols, 512 threads = 16 warps (4 M x 4 N of 32x64).
// AFP32: A fp32 in gmem, converted to fp16 in smem (register-prefetched).
//        else A fp16 in gmem, staged via cp.async.
// EFILL: blocks with blockIdx.x >= gemm_blocks build the ELL adjacency
//        (atomic slot alloc) — they schedule into the GEMM tail waves.
// ---------------------------------------------------------------------------
template <int K, bool AFP32, bool EFILL>
__global__ __launch_bounds__(512, 1) void mma_gemm_kernel(
    const float* __restrict__ A,
    const __half* __restrict__ Ah,
    const __half* __restrict__ Bs, const __half* __restrict__ Bn,
    float* __restrict__ Cs, __half* __restrict__ Cz, int n,
    int gemm_blocks, const int* __restrict__ rows,
    const int* __restrict__ cols, int e) {
    // ---- ELL-fill role (tail blocks) ----
    if (EFILL && (int)blockIdx.x >= gemm_blocks) {
        const int fb  = blockIdx.x - gemm_blocks;
        const int nfb = gridDim.x - gemm_blocks;
        const int tid = threadIdx.x;
        const int total4 = e >> 2;
        const int4* r4p = (const int4*)rows;
        const int4* c4p = (const int4*)cols;
        for (int i = fb * 512 + tid; i < total4; i += nfb * 512) {
            int4 r = __ldg(&r4p[i]);
            int4 c = __ldg(&c4p[i]);
            int p;
            p = atomicAdd(&g_cnt[r.x], 1); if (p < ELLW) g_ell[(size_t)r.x * ELLW + p] = c.x;
            p = atomicAdd(&g_cnt[r.y], 1); if (p < ELLW) g_ell[(size_t)r.y * ELLW + p] = c.y;
            p = atomicAdd(&g_cnt[r.z], 1); if (p < ELLW) g_ell[(size_t)r.z * ELLW + p] = c.z;
            p = atomicAdd(&g_cnt[r.w], 1); if (p < ELLW) g_ell[(size_t)r.w * ELLW + p] = c.w;
        }
        if (fb == 0) {       // scalar tail (e % 4)
            for (int i = (total4 << 2) + tid; i < e; i += 512) {
                int r = __ldg(&rows[i]), c = __ldg(&cols[i]);
                int p = atomicAdd(&g_cnt[r], 1);
                if (p < ELLW) g_ell[(size_t)r * ELLW + p] = c;
            }
        }
        return;
    }

    extern __shared__ char smem[];
    constexpr int BUF  = 49152;          // A 16K + Bs 16K + Bn 16K
    constexpr int AOFF = 0;
    constexpr int BOFF = 16384;
    constexpr int NC   = K / 64;
    const uint32_t sb = smem_u32(smem);
    const int tid    = threadIdx.x;
    const int lane   = tid & 31;
    const int wid    = tid >> 5;
    const int warp_m = wid & 3;
    const int warp_n = wid >> 2;
    const int row0   = blockIdx.x * 128;

    float acc[2][8][4];
    #pragma unroll
    for (int m = 0; m < 2; ++m)
        #pragma unroll
        for (int f = 0; f < 8; ++f)
            #pragma unroll
            for (int q = 0; q < 4; ++q) acc[m][f][q] = 0.f;

    auto stage_B = [&](int c, int buf) {
        #pragma unroll
        for (int t = 0; t < 2; ++t) {
            const __half* B = t ? Bn : Bs;
            #pragma unroll
            for (int i = tid; i < 1024; i += 512) {
                int row = i >> 3, j = i & 7;
                cp16(sb + buf * BUF + BOFF + t * 16384 + SWZ((uint32_t)(row * 128 + j * 16)),
                     B + (size_t)row * K + c * 64 + j * 8);
            }
        }
    };
    auto stage_A_async = [&](int c, int buf) {
        #pragma unroll
        for (int i = tid; i < 1024; i += 512) {
            int row = i >> 3, j = i & 7;
            cp16(sb + buf * BUF + AOFF + SWZ((uint32_t)(row * 128 + j * 16)),
                 Ah + (size_t)(row0 + row) * K + c * 64 + j * 8);
        }
    };
    float ar[2][8];
    auto load_A_regs = [&](int c) {
        #pragma unroll
        for (int t = 0; t < 2; ++t) {
            int g = tid + t * 512;
            int row = g >> 3, j = g & 7;
            int grow = row0 + row;
            float4 f0 = make_float4(0.f, 0.f, 0.f, 0.f), f1 = f0;
            if (grow < n) {
                const float* ap = A + (size_t)grow * K + c * 64 + j * 8;
                f0 = *(const float4*)ap;
                f1 = *(const float4*)(ap + 4);
            }
            ar[t][0] = f0.x; ar[t][1] = f0.y; ar[t][2] = f0.z; ar[t][3] = f0.w;
            ar[t][4] = f1.x; ar[t][5] = f1.y; ar[t][6] = f1.z; ar[t][7] = f1.w;
        }
    };
    auto convert_store_A = [&](int buf) {
        #pragma unroll
        for (int t = 0; t < 2; ++t) {
            int g = tid + t * 512;
            int row = g >> 3, j = g & 7;
            uint32_t hv[4];
            #pragma unroll
            for (int q = 0; q < 4; ++q) {
                __half2 hp = __floats2half2_rn(ar[t][2 * q], ar[t][2 * q + 1]);
                hv[q] = *reinterpret_cast<uint32_t*>(&hp);
            }
            *(uint4*)(smem + buf * BUF + AOFF + SWZ((uint32_t)(row * 128 + j * 16))) =
                make_uint4(hv[0], hv[1], hv[2], hv[3]);
        }
    };

    const uint32_t b_tile = BOFF + (warp_n >> 1) * 16384;   // Bs or Bn tile
    const int b_row_base = (warp_n & 1) * 64 + ((lane >> 4) << 3) + (lane & 7);
    const uint32_t b_colb = ((lane >> 3) & 1) * 16;

    stage_B(0, 0);
    if (!AFP32) {
        stage_A_async(0, 0);
        CP_COMMIT();
    } else {
        CP_COMMIT();
        load_A_regs(0);
        convert_store_A(0);
    }
    CP_WAIT0();
    __syncthreads();

    for (int c = 0; c < NC; ++c) {
        const int buf = c & 1, nb = buf ^ 1;
        const bool has_next = (c + 1 < NC);
        if (has_next) {
            stage_B(c + 1, nb);
            if (!AFP32) stage_A_async(c + 1, nb);
            CP_COMMIT();
            if (AFP32) load_A_regs(c + 1);
        }

        const uint32_t abase = sb + buf * BUF + AOFF;
        const uint32_t bbase = sb + buf * BUF + b_tile;
        #pragma unroll
        for (int ks = 0; ks < 4; ++ks) {
            uint32_t af[2][4];
            #pragma unroll
            for (int m = 0; m < 2; ++m) {
                uint32_t off = SWZ((uint32_t)((warp_m * 32 + m * 16 + (lane & 15)) * 128
                                              + (((lane >> 4) << 3) + ks * 16) * 2));
                ldsm_x4(abase + off, af[m][0], af[m][1], af[m][2], af[m][3]);
            }
            #pragma unroll
            for (int p = 0; p < 4; ++p) {
                uint32_t off = SWZ((uint32_t)((b_row_base + p * 16) * 128
                                              + ks * 32 + b_colb));
                uint32_t b0, b1, b2, b3;
                ldsm_x4(bbase + off, b0, b1, b2, b3);
                #pragma unroll
                for (int m = 0; m < 2; ++m) {
                    mma_fp16(acc[m][p * 2 + 0], af[m], b0, b1);
                    mma_fp16(acc[m][p * 2 + 1], af[m], b2, b3);
                }
            }
        }

        if (has_next) {
            if (AFP32) convert_store_A(nb);
            CP_WAIT0();
        }
        __syncthreads();
    }

    const bool is_z = warp_n >= 2;
    const int coln0 = (warp_n & 1) * 64;
    #pragma unroll
    for (int m = 0; m < 2; ++m) {
        int r0 = row0 + warp_m * 32 + m * 16 + (lane >> 2);
        int r1 = r0 + 8;
        #pragma unroll
        for (int f = 0; f < 8; ++f) {
            int col = coln0 + f * 8 + (lane & 3) * 2;
            if (is_z) {
                if (r0 < n)
                    *(__half2*)(Cz + (size_t)r0 * 128 + col) =
                        __floats2half2_rn(acc[m][f][0], acc[m][f][1]);
                if (r1 < n)
                    *(__half2*)(Cz + (size_t)r1 * 128 + col) =
                        __floats2half2_rn(acc[m][f][2], acc[m][f][3]);
            } else {
                if (r0 < n)
                    *(float2*)(Cs + (size_t)r0 * 128 + col) =
                        make_float2(acc[m][f][0], acc[m][f][1]);
                if (r1 < n)
                    *(float2*)(Cs + (size_t)r1 * 128 + col) =
                        make_float2(acc[m][f][2], acc[m][f][3]);
            }
        }
    }
}

// ---------------------------------------------------------------------------
// Warp-level gather over ELL row: int4 index loads (4 edges per load).
// ---------------------------------------------------------------------------
__device__ __forceinline__ void gather_row(const uint2* __restrict__ zp,
                                           const int* __restrict__ ell, int len,
                                           int lane,
                                           float& a0, float& a1,
                                           float& a2, float& a3) {
    int k = 0;
    for (; k + 3 < len; k += 4) {
        int4 j4 = __ldg((const int4*)(ell + k));       // 16B-aligned (k%4==0)
        uint2 u0 = __ldg(&zp[(size_t)j4.x * 32 + lane]);
        uint2 u1 = __ldg(&zp[(size_t)j4.y * 32 + lane]);
        uint2 u2 = __ldg(&zp[(size_t)j4.z * 32 + lane]);
        uint2 u3 = __ldg(&zp[(size_t)j4.w * 32 + lane]);
        float2 f;
        f = __half22float2(*(const __half2*)&u0.x); a0 += f.x; a1 += f.y;
        f = __half22float2(*(const __half2*)&u0.y); a2 += f.x; a3 += f.y;
        f = __half22float2(*(const __half2*)&u1.x); a0 += f.x; a1 += f.y;
        f = __half22float2(*(const __half2*)&u1.y); a2 += f.x; a3 += f.y;
        f = __half22float2(*(const __half2*)&u2.x); a0 += f.x; a1 += f.y;
        f = __half22float2(*(const __half2*)&u2.y); a2 += f.x; a3 += f.y;
        f = __half22float2(*(const __half2*)&u3.x); a0 += f.x; a1 += f.y;
        f = __half22float2(*(const __half2*)&u3.y); a2 += f.x; a3 += f.y;
    }
    for (; k < len; ++k) {
        int j0 = __ldg(&ell[k]);
        uint2 u0 = __ldg(&zp[(size_t)j0 * 32 + lane]);
        float2 f;
        f = __half22float2(*(const __half2*)&u0.x); a0 += f.x; a1 += f.y;
        f = __half22float2(*(const __half2*)&u0.y); a2 += f.x; a3 += f.y;
    }
}

// ---------------------------------------------------------------------------
// SpMM1: h1 = relu(s + gather/(deg+1)), written fp16 (GEMM2 A operand).
// ---------------------------------------------------------------------------
__global__ __launch_bounds__(256) void spmm1_kernel(
    const __half* __restrict__ z, const float* __restrict__ s,
    __half* __restrict__ h1, int n) {
    int w = (blockIdx.x * blockDim.x + threadIdx.x) >> 5;
    if (w >= n) return;
    int lane = threadIdx.x & 31;
    int deg = __ldg(&g_cnt[w]);
    int len = min(deg, ELLW);
    float a0 = 0.f, a1 = 0.f, a2 = 0.f, a3 = 0.f;
    gather_row((const uint2*)z, g_ell + (size_t)w * ELLW, len, lane, a0, a1, a2, a3);
    float inv = 1.0f / (float)(deg + 1);
    float4 sv = __ldg(&((const float4*)s)[(size_t)w * 32 + lane]);
    float o0 = fmaxf(sv.x + a0 * inv, 0.f);
    float o1 = fmaxf(sv.y + a1 * inv, 0.f);
    float o2 = fmaxf(sv.z + a2 * inv, 0.f);
    float o3 = fmaxf(sv.w + a3 * inv, 0.f);
    __half2 p0 = __floats2half2_rn(o0, o1);
    __half2 p1 = __floats2half2_rn(o2, o3);
    ((uint2*)h1)[(size_t)w * 32 + lane] =
        make_uint2(*reinterpret_cast<uint32_t*>(&p0),
                   *reinterpret_cast<uint32_t*>(&p1));
}

// ---------------------------------------------------------------------------
// SpMM2 + MLP + log_softmax fused. Warp per node.
// ---------------------------------------------------------------------------
__global__ __launch_bounds__(256) void spmm2_mlp_kernel(
    const __half* __restrict__ z, const float* __restrict__ s,
    const float* __restrict__ W, const float* __restrict__ bias,
    float* __restrict__ out, int n) {
    __shared__ float Ws[NCLASS * 129];    // bank = (c + k) % 32, conflict-free
    __shared__ float rowbuf[8][136];
    const int tid = threadIdx.x;
    for (int i = tid; i < NCLASS * 128; i += 256) {
        int c = i >> 7, k = i & 127;
        Ws[c * 129 + k] = W[i];
    }
    __syncthreads();

    const int lane = tid & 31;
    const int wid  = tid >> 5;
    int w = blockIdx.x * 8 + wid;
    if (w >= n) return;

    int deg = __ldg(&g_cnt[w]);
    int len = min(deg, ELLW);
    float a0 = 0.f, a1 = 0.f, a2 = 0.f, a3 = 0.f;
    gather_row((const uint2*)z, g_ell + (size_t)w * ELLW, len, lane, a0, a1, a2, a3);
    float inv = 1.0f / (float)(deg + 1);
    float4 sv = __ldg(&((const float4*)s)[(size_t)w * 32 + lane]);
    float o0 = fmaxf(sv.x + a0 * inv, 0.f);
    float o1 = fmaxf(sv.y + a1 * inv, 0.f);
    float o2 = fmaxf(sv.z + a2 * inv, 0.f);
    float o3 = fmaxf(sv.w + a3 * inv, 0.f);

    *(float4*)&rowbuf[wid][lane * 4] = make_float4(o0, o1, o2, o3);
    __syncwarp();

    float v0 = __ldg(&bias[lane]);
    float v1 = (lane < NCLASS - 32) ? __ldg(&bias[lane + 32]) : 0.f;
    const float* hr = rowbuf[wid];
    #pragma unroll 8
    for (int k = 0; k < 128; ++k) {
        float hh = hr[k];
        v0 = fmaf(hh, Ws[lane * 129 + k], v0);
        if (lane < 8) v1 = fmaf(hh, Ws[(lane + 32) * 129 + k], v1);
    }
    float m = v0;
    if (lane < 8) m = fmaxf(m, v1);
    #pragma unroll
    for (int off = 16; off >= 1; off >>= 1)
        m = fmaxf(m, __shfl_xor_sync(0xffffffffu, m, off));
    float sum = expf(v0 - m) + ((lane < 8) ? expf(v1 - m) : 0.f);
    #pragma unroll
    for (int off = 16; off >= 1; off >>= 1)
        sum += __shfl_xor_sync(0xffffffffu, sum, off);
    float ls = logf(sum);
    float* orow = out + (size_t)w * NCLASS;
    orow[lane] = v0 - m - ls;
    if (lane < 8) orow[32 + lane] = v1 - m - ls;
}

// ---------------------------------------------------------------------------
// Launch
// ---------------------------------------------------------------------------
extern "C" void kernel_launch(void* const* d_in, const int* in_sizes, int n_in,
                              void* d_out, int out_size) {
    const float* x    = (const float*)d_in[0];
    const float* W1   = (const float*)d_in[1];
    const float* W2   = (const float*)d_in[2];
    const float* mlpW = (const float*)d_in[3];
    const float* mlpb = (const float*)d_in[4];
    const int*   rows = (const int*)d_in[5];
    const int*   cols = (const int*)d_in[6];
    const int n = in_sizes[0] / NFEAT;
    const int e = in_sizes[5];
    float* out = (float*)d_out;

    void *p_s, *p_z, *p_h1, *p_w1s, *p_w1n, *p_w2s, *p_w2n;
    cudaGetSymbolAddress(&p_s, g_s);
    cudaGetSymbolAddress(&p_z, g_z);
    cudaGetSymbolAddress(&p_h1, g_h1);
    cudaGetSymbolAddress(&p_w1s, g_w1s);
    cudaGetSymbolAddress(&p_w1n, g_w1n);
    cudaGetSymbolAddress(&p_w2s, g_w2s);
    cudaGetSymbolAddress(&p_w2n, g_w2n);

    constexpr int SMEM = 2 * 49152;   // 96 KB double buffer
    cudaFuncSetAttribute((const void*)mma_gemm_kernel<256, true, true>,
                         cudaFuncAttributeMaxDynamicSharedMemorySize, SMEM);
    cudaFuncSetAttribute((const void*)mma_gemm_kernel<128, false, false>,
                         cudaFuncAttributeMaxDynamicSharedMemorySize, SMEM);

    int nsm = 148;
    cudaDeviceGetAttribute(&nsm, cudaDevAttrMultiProcessorCount, 0);

    // Prep: fp16 weight slices + degree-counter zero
    prep_kernel<<<(n + 255) / 256, 256>>>(W1, W2, n);

    const int gx = (n + 127) / 128;
    int fillb = (nsm - (gx % nsm)) + nsm;   // tail slots + one full wave
    const int spmm_blocks = (n * 32 + 255) / 256;

    // Layer 1 GEMM (+ELL build in tail blocks): s fp32, z fp16
    mma_gemm_kernel<256, true, true><<<gx + fillb, 512, SMEM>>>(
        x, nullptr, (const __half*)p_w1s, (const __half*)p_w1n,
        (float*)p_s, (__half*)p_z, n, gx, rows, cols, e);
    spmm1_kernel<<<spmm_blocks, 256>>>(
        (const __half*)p_z, (const float*)p_s, (__half*)p_h1, n);

    // Layer 2: A = h1 fp16 (pure cp.async path)
    mma_gemm_kernel<128, false, false><<<gx, 512, SMEM>>>(
        nullptr, (const __half*)p_h1, (const __half*)p_w2s, (const __half*)p_w2n,
        (float*)p_s, (__half*)p_z, n, gx, nullptr, nullptr, 0);

    // SpMM2 + MLP + log_softmax fused
    spmm2_mlp_kernel<<<(n + 7) / 8, 256>>>(
        (const __half*)p_z, (const float*)p_s, mlpW, mlpb, out, n);
}